// round 5
// baseline (speedup 1.0000x reference)
#include <cuda_runtime.h>
#include <math.h>
#include <stdint.h>

// ---------------------------------------------------------------------------
// PreGatingContextualAttentionGate — round 5
// tf32 tensor cores everywhere; scores = single-pass tf32 (RN-rounded frags),
// all other GEMMs = tf32x3 split (fp32-equivalent accuracy).
// Fixes round-4 failure: raw-fp32-bits-as-tf32 caused coherent RZ truncation
// bias (~-5e-4/GEMM) compounding over the 6-GEMM chain to 4.3e-3.
// B=4, N=4096, D=DK=256, OUT=128
// d_out layout: [ out1 = Qf + C : 4*4096*128 f32 ][ attn : 4*4096*4096 f32 ]
// ---------------------------------------------------------------------------

#define NTHREADS 256

static constexpr int    BATCH = 4;
static constexpr int    NSEQ  = 4096;
static constexpr int    D     = 256;
static constexpr int    OUTC  = 128;
static constexpr size_t ROWS  = (size_t)BATCH * NSEQ;             // 16384
static constexpr size_t QK_ELEMS   = ROWS * D;                    // 4 M
static constexpr size_t S_ELEMS    = (size_t)BATCH * NSEQ * NSEQ; // 67 M
static constexpr size_t OUT1_ELEMS = ROWS * OUTC;                 // 2 M

// tc tiling
static constexpr int KC     = 32;            // k-chunk
static constexpr int LDT    = 36;            // padded smem row stride (floats)
static constexpr int TILE_F = 128 * LDT;     // floats per 128x32 tile buffer

// Scratch (static device arrays — the sanctioned workaround)
__device__ float g_Q [QK_ELEMS];
__device__ float g_K [QK_ELEMS];
__device__ float g_V [QK_ELEMS];
__device__ float g_tQ[QK_ELEMS];
__device__ float g_tK[QK_ELEMS];
__device__ float g_S [S_ELEMS];
__device__ float g_Qhat[QK_ELEMS];
__device__ float g_T1[OUT1_ELEMS];
__device__ float g_T2[OUT1_ELEMS];
__device__ float g_T3[OUT1_ELEMS];
__device__ float g_Qf[OUT1_ELEMS];
__device__ float g_GE[OUT1_ELEMS];

__device__ __forceinline__ float relu_f(float x) { return x > 0.f ? x : 0.f; }

// ---------------------------------------------------------------------------
// tf32 mma.sync helpers
// ---------------------------------------------------------------------------
__device__ __forceinline__ uint32_t f2tf(float f) {
    uint32_t u;
    asm("cvt.rna.tf32.f32 %0, %1;" : "=r"(u) : "f"(f));
    return u;
}

__device__ __forceinline__ void mma_tf32(float* d, const uint32_t* a, const uint32_t* b) {
    asm volatile(
        "mma.sync.aligned.m16n8k8.row.col.f32.tf32.tf32.f32 "
        "{%0,%1,%2,%3}, {%4,%5,%6,%7}, {%8,%9}, {%0,%1,%2,%3};"
        : "+f"(d[0]), "+f"(d[1]), "+f"(d[2]), "+f"(d[3])
        : "r"(a[0]), "r"(a[1]), "r"(a[2]), "r"(a[3]), "r"(b[0]), "r"(b[1]));
}

__device__ __forceinline__ void cp16(uint32_t saddr, const void* g) {
    asm volatile("cp.async.cg.shared.global [%0], [%1], 16;" :: "r"(saddr), "l"(g));
}
__device__ __forceinline__ void cp_commit() { asm volatile("cp.async.commit_group;"); }
__device__ __forceinline__ void cp_wait1()  { asm volatile("cp.async.wait_group 1;"); }
__device__ __forceinline__ void cp_wait0()  { asm volatile("cp.async.wait_group 0;"); }

// cp.async one 128x32 row-major tile (k contiguous): 4 x 16B per thread.
__device__ __forceinline__ void tile_cp(const float* __restrict__ g, int ldg, int k0,
                                        uint32_t sbase /*bytes*/, int tid)
{
#pragma unroll
    for (int i = 0; i < 4; ++i) {
        const int fid = tid + i * 256;      // 0..1023
        const int row = fid >> 3;
        const int kq  = fid & 7;
        cp16(sbase + (uint32_t)(row * LDT + kq * 4) * 4,
             g + (size_t)row * ldg + k0 + kq * 4);
    }
}

// Transpose-load a 32(k) x 128(n) slice of row-major W[ldb cols] into SB[n][k],
// raw fp32 (precision handled at fragment load).
__device__ __forceinline__ void loadB_tr(const float* __restrict__ W, int ldb, int nb,
                                         int k0, float* __restrict__ dst, int tid)
{
#pragma unroll
    for (int i = 0; i < 4; ++i) {
        const int idx = tid + i * 256;   // 0..1023
        const int n  = idx & 127;
        const int kg = (idx >> 7) * 4;   // 0,4,...,28
        const float* src = W + (size_t)(k0 + kg) * ldb + nb + n;
        float4 u;
        u.x = src[0];
        u.y = src[(size_t)ldb];
        u.z = src[(size_t)2 * ldb];
        u.w = src[(size_t)3 * ldb];
        *reinterpret_cast<float4*>(dst + n * LDT + kg) = u;
    }
}

// ---- fragment loads from smem tile [row][LDT] ----
// single-pass (RN-rounded tf32)
__device__ __forceinline__ void ldfragA_rn(const float* __restrict__ s, int row0, int kc,
                                           int gid, int tig, uint32_t* a)
{
    a[0] = f2tf(s[(row0 + gid)     * LDT + kc + tig]);
    a[1] = f2tf(s[(row0 + gid + 8) * LDT + kc + tig]);
    a[2] = f2tf(s[(row0 + gid)     * LDT + kc + 4 + tig]);
    a[3] = f2tf(s[(row0 + gid + 8) * LDT + kc + 4 + tig]);
}
__device__ __forceinline__ void ldfragB_rn(const float* __restrict__ s, int n0, int kc,
                                           int gid, int tig, uint32_t* b)
{
    b[0] = f2tf(s[(n0 + gid) * LDT + kc + tig]);
    b[1] = f2tf(s[(n0 + gid) * LDT + kc + 4 + tig]);
}
// tf32x3 hi/lo split
__device__ __forceinline__ void split_tf(float v, uint32_t& h, uint32_t& l) {
    h = f2tf(v);
    l = f2tf(v - __uint_as_float(h));
}
__device__ __forceinline__ void ldfragA_sp(const float* __restrict__ s, int row0, int kc,
                                           int gid, int tig, uint32_t* ah, uint32_t* al)
{
    split_tf(s[(row0 + gid)     * LDT + kc + tig],     ah[0], al[0]);
    split_tf(s[(row0 + gid + 8) * LDT + kc + tig],     ah[1], al[1]);
    split_tf(s[(row0 + gid)     * LDT + kc + 4 + tig], ah[2], al[2]);
    split_tf(s[(row0 + gid + 8) * LDT + kc + 4 + tig], ah[3], al[3]);
}
__device__ __forceinline__ void ldfragB_sp(const float* __restrict__ s, int n0, int kc,
                                           int gid, int tig, uint32_t* bh, uint32_t* bl)
{
    split_tf(s[(n0 + gid) * LDT + kc + tig],     bh[0], bl[0]);
    split_tf(s[(n0 + gid) * LDT + kc + 4 + tig], bh[1], bl[1]);
}

// One 128x128x32 chunk, single-pass tf32 (RN)
__device__ __forceinline__ void mma_chunk_rn(const float* __restrict__ cA,
                                             const float* __restrict__ cB,
                                             int warp_m, int warp_n, int gid, int tig,
                                             float (&acc)[4][4][4])
{
#pragma unroll
    for (int ks = 0; ks < 4; ++ks) {
        const int kc = ks * 8;
        uint32_t af[4][4], bf[4][2];
#pragma unroll
        for (int mt = 0; mt < 4; ++mt) ldfragA_rn(cA, warp_m + mt * 16, kc, gid, tig, af[mt]);
#pragma unroll
        for (int ntl = 0; ntl < 4; ++ntl) ldfragB_rn(cB, warp_n + ntl * 8, kc, gid, tig, bf[ntl]);
#pragma unroll
        for (int mt = 0; mt < 4; ++mt)
#pragma unroll
            for (int ntl = 0; ntl < 4; ++ntl)
                mma_tf32(acc[mt][ntl], af[mt], bf[ntl]);
    }
}

// One 128x128x32 chunk, tf32x3 (fp32-equivalent): ah*bh + al*bh + ah*bl
__device__ __forceinline__ void mma_chunk_x3(const float* __restrict__ cA,
                                             const float* __restrict__ cB,
                                             int warp_m, int warp_n, int gid, int tig,
                                             float (&acc)[4][4][4])
{
#pragma unroll
    for (int ks = 0; ks < 4; ++ks) {
        const int kc = ks * 8;
        uint32_t ah[4][4], al[4][4], bh[4][2], bl[4][2];
#pragma unroll
        for (int mt = 0; mt < 4; ++mt) ldfragA_sp(cA, warp_m + mt * 16, kc, gid, tig, ah[mt], al[mt]);
#pragma unroll
        for (int ntl = 0; ntl < 4; ++ntl) ldfragB_sp(cB, warp_n + ntl * 8, kc, gid, tig, bh[ntl], bl[ntl]);
#pragma unroll
        for (int mt = 0; mt < 4; ++mt)
#pragma unroll
            for (int ntl = 0; ntl < 4; ++ntl) {
                mma_tf32(acc[mt][ntl], al[mt], bh[ntl]);
                mma_tf32(acc[mt][ntl], ah[mt], bl[ntl]);
                mma_tf32(acc[mt][ntl], ah[mt], bh[ntl]);
            }
    }
}

// ---------------------------------------------------------------------------
// Fused scores (tc, single-pass RN): S = (Q·K^T) * (tanhQ·tanhK^T + 1) * 0.03125
// CTA 128x128, 8 warps (2x4), warp 64x32. grid (32, 32, 4). smem 147456 B.
// ---------------------------------------------------------------------------
__global__ void __launch_bounds__(NTHREADS)
scores_tc_kernel(const float* __restrict__ Qm, const float* __restrict__ Km,
                 const float* __restrict__ tQm, const float* __restrict__ tKm,
                 float* __restrict__ S)
{
    extern __shared__ float sm[];
    float* SA1 = sm;
    float* SB1 = sm + 2 * TILE_F;
    float* SA2 = sm + 4 * TILE_F;
    float* SB2 = sm + 6 * TILE_F;
    const uint32_t a1b = (uint32_t)__cvta_generic_to_shared(SA1);
    const uint32_t b1b = (uint32_t)__cvta_generic_to_shared(SB1);
    const uint32_t a2b = (uint32_t)__cvta_generic_to_shared(SA2);
    const uint32_t b2b = (uint32_t)__cvta_generic_to_shared(SB2);

    const int tid  = threadIdx.x;
    const int wid  = tid >> 5;
    const int lane = tid & 31;
    const int gid  = lane >> 2;
    const int tig  = lane & 3;
    const int warp_m = (wid & 1) * 64;
    const int warp_n = (wid >> 1) * 32;

    const int b  = blockIdx.z;
    const int mb = blockIdx.y * 128;
    const int nb = blockIdx.x * 128;
    const float* A1 = Qm  + (size_t)b * NSEQ * D + (size_t)mb * D;
    const float* B1 = Km  + (size_t)b * NSEQ * D + (size_t)nb * D;
    const float* A2 = tQm + (size_t)b * NSEQ * D + (size_t)mb * D;
    const float* B2 = tKm + (size_t)b * NSEQ * D + (size_t)nb * D;

    float acc1[4][4][4] = {};
    float acc2[4][4][4] = {};

    const int nt = D / KC; // 8
    const uint32_t bufB = (uint32_t)TILE_F * 4;

    tile_cp(A1, D, 0, a1b, tid);
    tile_cp(B1, D, 0, b1b, tid);
    tile_cp(A2, D, 0, a2b, tid);
    tile_cp(B2, D, 0, b2b, tid);
    cp_commit();

    for (int t = 0; t < nt; ++t) {
        const int cur = t & 1;
        if (t + 1 < nt) {
            const int k0 = (t + 1) * KC;
            const uint32_t off = (uint32_t)((t + 1) & 1) * bufB;
            tile_cp(A1, D, k0, a1b + off, tid);
            tile_cp(B1, D, k0, b1b + off, tid);
            tile_cp(A2, D, k0, a2b + off, tid);
            tile_cp(B2, D, k0, b2b + off, tid);
            cp_commit();
            cp_wait1();
        } else {
            cp_wait0();
        }
        __syncthreads();

        mma_chunk_rn(SA1 + cur * TILE_F, SB1 + cur * TILE_F, warp_m, warp_n, gid, tig, acc1);
        mma_chunk_rn(SA2 + cur * TILE_F, SB2 + cur * TILE_F, warp_m, warp_n, gid, tig, acc2);
        __syncthreads();
    }

    float* Sb = S + (size_t)b * NSEQ * NSEQ;
#pragma unroll
    for (int mt = 0; mt < 4; ++mt) {
        const int row = mb + warp_m + mt * 16 + gid;
#pragma unroll
        for (int ntl = 0; ntl < 4; ++ntl) {
            const int col = nb + warp_n + ntl * 8 + tig * 2;
            const float* a1 = acc1[mt][ntl];
            const float* a2 = acc2[mt][ntl];
            float2 v0 = make_float2(a1[0] * (a2[0] + 1.f) * 0.03125f,
                                    a1[1] * (a2[1] + 1.f) * 0.03125f);
            float2 v1 = make_float2(a1[2] * (a2[2] + 1.f) * 0.03125f,
                                    a1[3] * (a2[3] + 1.f) * 0.03125f);
            *reinterpret_cast<float2*>(Sb + (size_t)row * NSEQ + col)       = v0;
            *reinterpret_cast<float2*>(Sb + (size_t)(row + 8) * NSEQ + col) = v1;
        }
    }
}

// ---------------------------------------------------------------------------
// PV (tc, tf32x3): Qhat[b] = attn_b [4096,4096] @ V_b [4096,256].
// grid (2, 32, 4). smem 73728 B.
// ---------------------------------------------------------------------------
__global__ void __launch_bounds__(NTHREADS)
pv_tc_kernel(const float* __restrict__ attn, const float* __restrict__ V,
             float* __restrict__ Qhat)
{
    extern __shared__ float sm[];
    float* SA = sm;
    float* SB = sm + 2 * TILE_F;
    const uint32_t ab = (uint32_t)__cvta_generic_to_shared(SA);

    const int tid  = threadIdx.x;
    const int wid  = tid >> 5;
    const int lane = tid & 31;
    const int gid  = lane >> 2;
    const int tig  = lane & 3;
    const int warp_m = (wid & 1) * 64;
    const int warp_n = (wid >> 1) * 32;

    const int b  = blockIdx.z;
    const int mb = blockIdx.y * 128;
    const int nb = blockIdx.x * 128;
    const float* Ab = attn + (size_t)b * NSEQ * NSEQ + (size_t)mb * NSEQ;
    const float* Vb = V + (size_t)b * NSEQ * D;

    float acc[4][4][4] = {};
    const int nt = NSEQ / KC; // 128
    const uint32_t bufB = (uint32_t)TILE_F * 4;

    tile_cp(Ab, NSEQ, 0, ab, tid);
    cp_commit();
    loadB_tr(Vb, D, nb, 0, SB, tid);

    for (int t = 0; t < nt; ++t) {
        const int cur = t & 1;
        if (t + 1 < nt) {
            const int k0 = (t + 1) * KC;
            tile_cp(Ab, NSEQ, k0, ab + (uint32_t)((t + 1) & 1) * bufB, tid);
            cp_commit();
            loadB_tr(Vb, D, nb, k0, SB + ((t + 1) & 1) * TILE_F, tid);
            cp_wait1();
        } else {
            cp_wait0();
        }
        __syncthreads();

        mma_chunk_x3(SA + cur * TILE_F, SB + cur * TILE_F, warp_m, warp_n, gid, tig, acc);
        __syncthreads();
    }

    float* Qb = Qhat + (size_t)b * NSEQ * D;
#pragma unroll
    for (int mt = 0; mt < 4; ++mt) {
        const int row = mb + warp_m + mt * 16 + gid;
#pragma unroll
        for (int ntl = 0; ntl < 4; ++ntl) {
            const int col = nb + warp_n + ntl * 8 + tig * 2;
            const float* a = acc[mt][ntl];
            *reinterpret_cast<float2*>(Qb + (size_t)row * D + col)       = make_float2(a[0], a[1]);
            *reinterpret_cast<float2*>(Qb + (size_t)(row + 8) * D + col) = make_float2(a[2], a[3]);
        }
    }
}

// ---------------------------------------------------------------------------
// Projection (tc, tf32x3): Out = X @ W + bias, optional TOut = tanh(Out).
// X [16384,256], W [256,256]. grid (2, 128). smem 73728 B.
// ---------------------------------------------------------------------------
__global__ void __launch_bounds__(NTHREADS)
proj_tc_kernel(const float* __restrict__ X, const float* __restrict__ W,
               const float* __restrict__ bias,
               float* __restrict__ Out, float* __restrict__ TOut)
{
    extern __shared__ float sm[];
    float* SA = sm;
    float* SB = sm + 2 * TILE_F;
    const uint32_t ab = (uint32_t)__cvta_generic_to_shared(SA);

    const int tid  = threadIdx.x;
    const int wid  = tid >> 5;
    const int lane = tid & 31;
    const int gid  = lane >> 2;
    const int tig  = lane & 3;
    const int warp_m = (wid & 1) * 64;
    const int warp_n = (wid >> 1) * 32;

    const int mb = blockIdx.y * 128;
    const int nb = blockIdx.x * 128;
    const float* A = X + (size_t)mb * D;

    float acc[4][4][4] = {};
    const int nt = D / KC; // 8
    const uint32_t bufB = (uint32_t)TILE_F * 4;

    tile_cp(A, D, 0, ab, tid);
    cp_commit();
    loadB_tr(W, D, nb, 0, SB, tid);

    for (int t = 0; t < nt; ++t) {
        const int cur = t & 1;
        if (t + 1 < nt) {
            const int k0 = (t + 1) * KC;
            tile_cp(A, D, k0, ab + (uint32_t)((t + 1) & 1) * bufB, tid);
            cp_commit();
            loadB_tr(W, D, nb, k0, SB + ((t + 1) & 1) * TILE_F, tid);
            cp_wait1();
        } else {
            cp_wait0();
        }
        __syncthreads();
        mma_chunk_x3(SA + cur * TILE_F, SB + cur * TILE_F, warp_m, warp_n, gid, tig, acc);
        __syncthreads();
    }

#pragma unroll
    for (int mt = 0; mt < 4; ++mt) {
        const int row = mb + warp_m + mt * 16 + gid;
#pragma unroll
        for (int ntl = 0; ntl < 4; ++ntl) {
            const int col = nb + warp_n + ntl * 8 + tig * 2;
            const float* a = acc[mt][ntl];
            const float b0 = bias[col], b1 = bias[col + 1];
            float v00 = a[0] + b0, v01 = a[1] + b1;
            float v10 = a[2] + b0, v11 = a[3] + b1;
            *reinterpret_cast<float2*>(Out + (size_t)row * D + col)       = make_float2(v00, v01);
            *reinterpret_cast<float2*>(Out + (size_t)(row + 8) * D + col) = make_float2(v10, v11);
            if (TOut) {
                *reinterpret_cast<float2*>(TOut + (size_t)row * D + col)       = make_float2(tanhf(v00), tanhf(v01));
                *reinterpret_cast<float2*>(TOut + (size_t)(row + 8) * D + col) = make_float2(tanhf(v10), tanhf(v11));
            }
        }
    }
}

// ---------------------------------------------------------------------------
// Dual gate (tc, tf32x3): OutA = relu(X@Wa+ba), OutB = relu(X@Wb+bb).
// Shared A tiles+fragments. X [16384,256], W [256,128]. grid (1,128). smem 110592 B.
// ---------------------------------------------------------------------------
__global__ void __launch_bounds__(NTHREADS)
dualgate_tc_kernel(const float* __restrict__ X,
                   const float* __restrict__ Wa, const float* __restrict__ ba,
                   const float* __restrict__ Wb, const float* __restrict__ bb,
                   float* __restrict__ OutA, float* __restrict__ OutB)
{
    extern __shared__ float sm[];
    float* SA  = sm;
    float* SBa = sm + 2 * TILE_F;
    float* SBb = sm + 4 * TILE_F;
    const uint32_t ab = (uint32_t)__cvta_generic_to_shared(SA);

    const int tid  = threadIdx.x;
    const int wid  = tid >> 5;
    const int lane = tid & 31;
    const int gid  = lane >> 2;
    const int tig  = lane & 3;
    const int warp_m = (wid & 1) * 64;
    const int warp_n = (wid >> 1) * 32;

    const int mb = blockIdx.y * 128;
    const float* A = X + (size_t)mb * D;

    float accA[4][4][4] = {};
    float accB[4][4][4] = {};
    const int nt = D / KC; // 8
    const uint32_t bufB = (uint32_t)TILE_F * 4;

    tile_cp(A, D, 0, ab, tid);
    cp_commit();
    loadB_tr(Wa, OUTC, 0, 0, SBa, tid);
    loadB_tr(Wb, OUTC, 0, 0, SBb, tid);

    for (int t = 0; t < nt; ++t) {
        const int cur = t & 1;
        if (t + 1 < nt) {
            const int k0 = (t + 1) * KC;
            const int nxt = (t + 1) & 1;
            tile_cp(A, D, k0, ab + (uint32_t)nxt * bufB, tid);
            cp_commit();
            loadB_tr(Wa, OUTC, 0, k0, SBa + nxt * TILE_F, tid);
            loadB_tr(Wb, OUTC, 0, k0, SBb + nxt * TILE_F, tid);
            cp_wait1();
        } else {
            cp_wait0();
        }
        __syncthreads();

        const float* cA  = SA  + cur * TILE_F;
        const float* cBa = SBa + cur * TILE_F;
        const float* cBb = SBb + cur * TILE_F;
#pragma unroll
        for (int ks = 0; ks < 4; ++ks) {
            const int kc = ks * 8;
            uint32_t ah[4][4], al[4][4];
#pragma unroll
            for (int mt = 0; mt < 4; ++mt) ldfragA_sp(cA, warp_m + mt * 16, kc, gid, tig, ah[mt], al[mt]);
            // Wa pass
            {
                uint32_t bh[4][2], bl[4][2];
#pragma unroll
                for (int ntl = 0; ntl < 4; ++ntl) ldfragB_sp(cBa, warp_n + ntl * 8, kc, gid, tig, bh[ntl], bl[ntl]);
#pragma unroll
                for (int mt = 0; mt < 4; ++mt)
#pragma unroll
                    for (int ntl = 0; ntl < 4; ++ntl) {
                        mma_tf32(accA[mt][ntl], al[mt], bh[ntl]);
                        mma_tf32(accA[mt][ntl], ah[mt], bl[ntl]);
                        mma_tf32(accA[mt][ntl], ah[mt], bh[ntl]);
                    }
            }
            // Wb pass
            {
                uint32_t bh[4][2], bl[4][2];
#pragma unroll
                for (int ntl = 0; ntl < 4; ++ntl) ldfragB_sp(cBb, warp_n + ntl * 8, kc, gid, tig, bh[ntl], bl[ntl]);
#pragma unroll
                for (int mt = 0; mt < 4; ++mt)
#pragma unroll
                    for (int ntl = 0; ntl < 4; ++ntl) {
                        mma_tf32(accB[mt][ntl], al[mt], bh[ntl]);
                        mma_tf32(accB[mt][ntl], ah[mt], bl[ntl]);
                        mma_tf32(accB[mt][ntl], ah[mt], bh[ntl]);
                    }
            }
        }
        __syncthreads();
    }

#pragma unroll
    for (int mt = 0; mt < 4; ++mt) {
        const int row = mb + warp_m + mt * 16 + gid;
#pragma unroll
        for (int ntl = 0; ntl < 4; ++ntl) {
            const int col = warp_n + ntl * 8 + tig * 2;
            const float* a = accA[mt][ntl];
            const float* c = accB[mt][ntl];
            float a0 = ba[col], a1 = ba[col + 1];
            float c0 = bb[col], c1 = bb[col + 1];
            *reinterpret_cast<float2*>(OutA + (size_t)row * OUTC + col) =
                make_float2(relu_f(a[0] + a0), relu_f(a[1] + a1));
            *reinterpret_cast<float2*>(OutA + (size_t)(row + 8) * OUTC + col) =
                make_float2(relu_f(a[2] + a0), relu_f(a[3] + a1));
            *reinterpret_cast<float2*>(OutB + (size_t)row * OUTC + col) =
                make_float2(relu_f(c[0] + c0), relu_f(c[1] + c1));
            *reinterpret_cast<float2*>(OutB + (size_t)(row + 8) * OUTC + col) =
                make_float2(relu_f(c[2] + c0), relu_f(c[3] + c1));
        }
    }
}

// ---------------------------------------------------------------------------
// Final (tc, tf32x3): out1 = Qf + relu(GE @ Wc + bc). grid (1,128). smem 73728 B.
// ---------------------------------------------------------------------------
__global__ void __launch_bounds__(NTHREADS)
final_tc_kernel(const float* __restrict__ GE, const float* __restrict__ Wc,
                const float* __restrict__ bc, const float* __restrict__ Qf,
                float* __restrict__ Out)
{
    extern __shared__ float sm[];
    float* SA = sm;
    float* SB = sm + 2 * TILE_F;
    const uint32_t ab = (uint32_t)__cvta_generic_to_shared(SA);

    const int tid  = threadIdx.x;
    const int wid  = tid >> 5;
    const int lane = tid & 31;
    const int gid  = lane >> 2;
    const int tig  = lane & 3;
    const int warp_m = (wid & 1) * 64;
    const int warp_n = (wid >> 1) * 32;

    const int mb = blockIdx.y * 128;
    const float* A = GE + (size_t)mb * OUTC;

    float acc[4][4][4] = {};
    const int nt = OUTC / KC; // 4
    const uint32_t bufB = (uint32_t)TILE_F * 4;

    tile_cp(A, OUTC, 0, ab, tid);
    cp_commit();
    loadB_tr(Wc, OUTC, 0, 0, SB, tid);

    for (int t = 0; t < nt; ++t) {
        const int cur = t & 1;
        if (t + 1 < nt) {
            const int k0 = (t + 1) * KC;
            const int nxt = (t + 1) & 1;
            tile_cp(A, OUTC, k0, ab + (uint32_t)nxt * bufB, tid);
            cp_commit();
            loadB_tr(Wc, OUTC, 0, k0, SB + nxt * TILE_F, tid);
            cp_wait1();
        } else {
            cp_wait0();
        }
        __syncthreads();
        mma_chunk_x3(SA + cur * TILE_F, SB + cur * TILE_F, warp_m, warp_n, gid, tig, acc);
        __syncthreads();
    }

#pragma unroll
    for (int mt = 0; mt < 4; ++mt) {
        const int row = mb + warp_m + mt * 16 + gid;
#pragma unroll
        for (int ntl = 0; ntl < 4; ++ntl) {
            const int col = warp_n + ntl * 8 + tig * 2;
            const float* a = acc[mt][ntl];
            const float b0 = bc[col], b1 = bc[col + 1];
            const float* q0 = Qf + (size_t)row * OUTC + col;
            const float* q1 = Qf + (size_t)(row + 8) * OUTC + col;
            *reinterpret_cast<float2*>(Out + (size_t)row * OUTC + col) =
                make_float2(q0[0] + relu_f(a[0] + b0), q0[1] + relu_f(a[1] + b1));
            *reinterpret_cast<float2*>(Out + (size_t)(row + 8) * OUTC + col) =
                make_float2(q1[0] + relu_f(a[2] + b0), q1[1] + relu_f(a[3] + b1));
        }
    }
}

// ---------------------------------------------------------------------------
// Softmax: attn = softmax_row(S). one CTA per row. grid 16384
// ---------------------------------------------------------------------------
__global__ void __launch_bounds__(NTHREADS)
softmax_kernel(const float* __restrict__ S, float* __restrict__ attn)
{
    __shared__ float rowbuf[NSEQ];
    __shared__ float red[8];
    __shared__ float bcast;
    const size_t r = blockIdx.x;
    const float* ps = S + r * NSEQ;
    float* po = attn + r * NSEQ;
    const int tid = threadIdx.x;

    float m = -1e30f;
    for (int i = tid; i < NSEQ; i += NTHREADS) {
        float v = ps[i];
        rowbuf[i] = v;
        m = fmaxf(m, v);
    }
#pragma unroll
    for (int off = 16; off; off >>= 1) m = fmaxf(m, __shfl_xor_sync(0xffffffffu, m, off));
    if ((tid & 31) == 0) red[tid >> 5] = m;
    __syncthreads();
    if (tid < 8) {
        float mm = red[tid];
#pragma unroll
        for (int off = 4; off; off >>= 1) mm = fmaxf(mm, __shfl_xor_sync(0xffu, mm, off));
        if (tid == 0) bcast = mm;
    }
    __syncthreads();
    const float M = bcast;

    float s = 0.f;
    for (int i = tid; i < NSEQ; i += NTHREADS) {
        float e = __expf(rowbuf[i] - M);
        rowbuf[i] = e;
        s += e;
    }
#pragma unroll
    for (int off = 16; off; off >>= 1) s += __shfl_xor_sync(0xffffffffu, s, off);
    __syncthreads();
    if ((tid & 31) == 0) red[tid >> 5] = s;
    __syncthreads();
    if (tid < 8) {
        float ss = red[tid];
#pragma unroll
        for (int off = 4; off; off >>= 1) ss += __shfl_xor_sync(0xffu, ss, off);
        if (tid == 0) bcast = 1.0f / ss;
    }
    __syncthreads();
    const float inv = bcast;
    for (int i = tid; i < NSEQ; i += NTHREADS) po[i] = rowbuf[i] * inv;
}

// ---------------------------------------------------------------------------
// LayerNorm gate: GE = LN(relu(T1+T2)) * LN(relu(T3)). grid 16384, 128 thr
// ---------------------------------------------------------------------------
__global__ void __launch_bounds__(OUTC)
lngate_kernel(const float* __restrict__ T1, const float* __restrict__ T2,
              const float* __restrict__ T3,
              const float* __restrict__ gg, const float* __restrict__ gb,
              const float* __restrict__ eg, const float* __restrict__ eb,
              float* __restrict__ GE)
{
    __shared__ float2 red[4];
    const size_t r = blockIdx.x;
    const int c = threadIdx.x;

    float a = relu_f(T1[r * OUTC + c] + T2[r * OUTC + c]);
    float2 v = make_float2(a, a * a);
#pragma unroll
    for (int off = 16; off; off >>= 1) {
        v.x += __shfl_xor_sync(0xffffffffu, v.x, off);
        v.y += __shfl_xor_sync(0xffffffffu, v.y, off);
    }
    if ((c & 31) == 0) red[c >> 5] = v;
    __syncthreads();
    float sx = red[0].x + red[1].x + red[2].x + red[3].x;
    float sy = red[0].y + red[1].y + red[2].y + red[3].y;
    float mu  = sx * (1.f / OUTC);
    float var = sy * (1.f / OUTC) - mu * mu;
    float g = (a - mu) * rsqrtf(var + 1e-5f) * gg[c] + gb[c];

    float e0 = relu_f(T3[r * OUTC + c]);
    __syncthreads();
    v = make_float2(e0, e0 * e0);
#pragma unroll
    for (int off = 16; off; off >>= 1) {
        v.x += __shfl_xor_sync(0xffffffffu, v.x, off);
        v.y += __shfl_xor_sync(0xffffffffu, v.y, off);
    }
    if ((c & 31) == 0) red[c >> 5] = v;
    __syncthreads();
    sx = red[0].x + red[1].x + red[2].x + red[3].x;
    sy = red[0].y + red[1].y + red[2].y + red[3].y;
    float mu2  = sx * (1.f / OUTC);
    float var2 = sy * (1.f / OUTC) - mu2 * mu2;
    float e = (e0 - mu2) * rsqrtf(var2 + 1e-5f) * eg[c] + eb[c];

    GE[r * OUTC + c] = g * e;
}

// ---------------------------------------------------------------------------
// Launch
// ---------------------------------------------------------------------------
extern "C" void kernel_launch(void* const* d_in, const int* in_sizes, int n_in,
                              void* d_out, int out_size)
{
    const float* x1  = (const float*)d_in[0];
    const float* x2  = (const float*)d_in[1];
    const float* W_q = (const float*)d_in[2];  const float* b_q = (const float*)d_in[3];
    const float* W_k = (const float*)d_in[4];  const float* b_k = (const float*)d_in[5];
    const float* W_v = (const float*)d_in[6];  const float* b_v = (const float*)d_in[7];
    const float* W1  = (const float*)d_in[8];  const float* b1  = (const float*)d_in[9];
    const float* W2  = (const float*)d_in[10]; const float* b2  = (const float*)d_in[11];
    const float* W3  = (const float*)d_in[12]; const float* b3  = (const float*)d_in[13];
    const float* gg  = (const float*)d_in[14]; const float* gb  = (const float*)d_in[15];
    const float* eg  = (const float*)d_in[16]; const float* eb  = (const float*)d_in[17];
    const float* W_c = (const float*)d_in[18]; const float* b_c = (const float*)d_in[19];
    const float* W_f = (const float*)d_in[20]; const float* b_f = (const float*)d_in[21];

    float* out1 = (float*)d_out;
    float* attn = out1 + OUT1_ELEMS;

    void* p;
    cudaGetSymbolAddress(&p, g_Q);    float* Q    = (float*)p;
    cudaGetSymbolAddress(&p, g_K);    float* K    = (float*)p;
    cudaGetSymbolAddress(&p, g_V);    float* V    = (float*)p;
    cudaGetSymbolAddress(&p, g_tQ);   float* tQ   = (float*)p;
    cudaGetSymbolAddress(&p, g_tK);   float* tK   = (float*)p;
    cudaGetSymbolAddress(&p, g_S);    float* S    = (float*)p;
    cudaGetSymbolAddress(&p, g_Qhat); float* Qhat = (float*)p;
    cudaGetSymbolAddress(&p, g_T1);   float* T1   = (float*)p;
    cudaGetSymbolAddress(&p, g_T2);   float* T2   = (float*)p;
    cudaGetSymbolAddress(&p, g_T3);   float* T3   = (float*)p;
    cudaGetSymbolAddress(&p, g_Qf);   float* Qf   = (float*)p;
    cudaGetSymbolAddress(&p, g_GE);   float* GE   = (float*)p;

    const int smem8 = 8 * TILE_F * (int)sizeof(float);  // 147456
    const int smem6 = 6 * TILE_F * (int)sizeof(float);  // 110592
    const int smem4 = 4 * TILE_F * (int)sizeof(float);  // 73728
    cudaFuncSetAttribute(scores_tc_kernel,   cudaFuncAttributeMaxDynamicSharedMemorySize, smem8);
    cudaFuncSetAttribute(pv_tc_kernel,       cudaFuncAttributeMaxDynamicSharedMemorySize, smem4);
    cudaFuncSetAttribute(proj_tc_kernel,     cudaFuncAttributeMaxDynamicSharedMemorySize, smem4);
    cudaFuncSetAttribute(dualgate_tc_kernel, cudaFuncAttributeMaxDynamicSharedMemorySize, smem6);
    cudaFuncSetAttribute(final_tc_kernel,    cudaFuncAttributeMaxDynamicSharedMemorySize, smem4);

    dim3 blk(NTHREADS);

    // Projections (Q from x2; K, V from x1) — tf32x3, fp32-accurate
    proj_tc_kernel<<<dim3(2, 128), blk, smem4>>>(x2, W_q, b_q, Q, tQ);
    proj_tc_kernel<<<dim3(2, 128), blk, smem4>>>(x1, W_k, b_k, K, tK);
    proj_tc_kernel<<<dim3(2, 128), blk, smem4>>>(x1, W_v, b_v, V, nullptr);

    // Fused score GEMMs (single-pass tf32, RN) -> combined pre-softmax scores
    scores_tc_kernel<<<dim3(32, 32, 4), blk, smem8>>>(Q, K, tQ, tK, S);

    // Softmax -> attn (output)
    softmax_kernel<<<BATCH * NSEQ, blk>>>(S, attn);

    // Q_hat = attn @ V — tf32x3
    pv_tc_kernel<<<dim3(2, 32, 4), blk, smem4>>>(attn, V, Qhat);

    // Gate projections (shared-A dual GEMMs) — tf32x3
    dualgate_tc_kernel<<<dim3(1, 128), blk, smem6>>>(Q,    W1, b1, W_f, b_f, T1, Qf);
    dualgate_tc_kernel<<<dim3(1, 128), blk, smem6>>>(Qhat, W2, b2, W3,  b3,  T2, T3);

    // LayerNorms + gate product
    lngate_kernel<<<BATCH * NSEQ, OUTC>>>(T1, T2, T3, gg, gb, eg, eb, GE);

    // out1 = Qf + relu(GE @ Wc + bc) — tf32x3
    final_tc_kernel<<<dim3(1, 128), blk, smem4>>>(GE, W_c, b_c, Qf, out1);
}

// round 6
// speedup vs baseline: 1.3713x; 1.3713x over previous
#include <cuda_runtime.h>
#include <math.h>
#include <stdint.h>

// ---------------------------------------------------------------------------
// PreGatingContextualAttentionGate — round 6
// tf32 mma.sync everywhere. All cvt/split work hoisted out of mainloops:
//  - scores operands pre-rounded at projection epilogue (bit-identical to R5)
//  - x3 kernels split hi/lo at smem-store stage (bit-identical values to R5)
//  - fragment loads vectorized via consistent k-lane permutation (LDS.64)
//  - PV reduced tf32x3 -> x2 (attn split, V pre-rounded)
// B=4, N=4096, D=DK=256, OUT=128
// d_out layout: [ out1 = Qf + C : 4*4096*128 f32 ][ attn : 4*4096*4096 f32 ]
// ---------------------------------------------------------------------------

#define NTHREADS 256

static constexpr int    BATCH = 4;
static constexpr int    NSEQ  = 4096;
static constexpr int    D     = 256;
static constexpr int    OUTC  = 128;
static constexpr size_t ROWS  = (size_t)BATCH * NSEQ;             // 16384
static constexpr size_t QK_ELEMS   = ROWS * D;                    // 4 M
static constexpr size_t S_ELEMS    = (size_t)BATCH * NSEQ * NSEQ; // 67 M
static constexpr size_t OUT1_ELEMS = ROWS * OUTC;                 // 2 M

static constexpr int KC     = 32;            // k-chunk
static constexpr int LDT    = 40;            // padded smem row stride (floats)
static constexpr int TILE_F = 128 * LDT;     // floats per 128x32 tile buffer

// Scratch (static device arrays — the sanctioned workaround)
__device__ float g_Q  [QK_ELEMS];   // full fp32 Q (for gates)
__device__ float g_Qr [QK_ELEMS];   // tf32-rounded Q (for scores)
__device__ float g_Kr [QK_ELEMS];   // tf32-rounded K
__device__ float g_Vr [QK_ELEMS];   // tf32-rounded V (PV B operand)
__device__ float g_tQ [QK_ELEMS];   // tf32-rounded tanh(Q)
__device__ float g_tK [QK_ELEMS];   // tf32-rounded tanh(K)
__device__ float g_S  [S_ELEMS];
__device__ float g_Qhat[QK_ELEMS];
__device__ float g_T1 [OUT1_ELEMS];
__device__ float g_T2 [OUT1_ELEMS];
__device__ float g_T3 [OUT1_ELEMS];
__device__ float g_Qf [OUT1_ELEMS];
__device__ float g_GE [OUT1_ELEMS];

__device__ __forceinline__ float relu_f(float x) { return x > 0.f ? x : 0.f; }

// ---------------------------------------------------------------------------
// tf32 helpers
// ---------------------------------------------------------------------------
__device__ __forceinline__ uint32_t f2tf(float f) {
    uint32_t u;
    asm("cvt.rna.tf32.f32 %0, %1;" : "=r"(u) : "f"(f));
    return u;
}
__device__ __forceinline__ float tf_round(float f) { return __uint_as_float(f2tf(f)); }

__device__ __forceinline__ void mma_tf32(float* d, const uint32_t* a, const uint32_t* b) {
    asm volatile(
        "mma.sync.aligned.m16n8k8.row.col.f32.tf32.tf32.f32 "
        "{%0,%1,%2,%3}, {%4,%5,%6,%7}, {%8,%9}, {%0,%1,%2,%3};"
        : "+f"(d[0]), "+f"(d[1]), "+f"(d[2]), "+f"(d[3])
        : "r"(a[0]), "r"(a[1]), "r"(a[2]), "r"(a[3]), "r"(b[0]), "r"(b[1]));
}

__device__ __forceinline__ void cp16(uint32_t saddr, const void* g) {
    asm volatile("cp.async.cg.shared.global [%0], [%1], 16;" :: "r"(saddr), "l"(g));
}
__device__ __forceinline__ void cp_commit() { asm volatile("cp.async.commit_group;"); }
__device__ __forceinline__ void cp_wait1()  { asm volatile("cp.async.wait_group 1;"); }
__device__ __forceinline__ void cp_wait0()  { asm volatile("cp.async.wait_group 0;"); }

// cp.async one 128x32 row-major tile: 4 x 16B per thread.
__device__ __forceinline__ void tile_cp(const float* __restrict__ g, int ldg, int k0,
                                        uint32_t sbase, int tid)
{
#pragma unroll
    for (int i = 0; i < 4; ++i) {
        const int fid = tid + i * 256;
        const int row = fid >> 3;
        const int kq  = fid & 7;
        cp16(sbase + (uint32_t)(row * LDT + kq * 4) * 4,
             g + (size_t)row * ldg + k0 + kq * 4);
    }
}

// ---- LDG staging (A row-major tile; B transpose tile) ----
__device__ __forceinline__ void ldg_tileA(const float* __restrict__ A, int lda, int k0,
                                          int tid, float4* r)
{
#pragma unroll
    for (int i = 0; i < 4; ++i) {
        const int fid = tid + i * 256;
        const int row = fid >> 3;
        const int kq  = fid & 7;
        r[i] = *reinterpret_cast<const float4*>(A + (size_t)row * lda + k0 + kq * 4);
    }
}
__device__ __forceinline__ void sts_tileA_split(float* __restrict__ hi, float* __restrict__ lo,
                                                int tid, const float4* r)
{
#pragma unroll
    for (int i = 0; i < 4; ++i) {
        const int fid = tid + i * 256;
        const int row = fid >> 3;
        const int kq  = fid & 7;
        float4 h, l;
        h.x = tf_round(r[i].x); l.x = r[i].x - h.x;
        h.y = tf_round(r[i].y); l.y = r[i].y - h.y;
        h.z = tf_round(r[i].z); l.z = r[i].z - h.z;
        h.w = tf_round(r[i].w); l.w = r[i].w - h.w;
        *reinterpret_cast<float4*>(hi + row * LDT + kq * 4) = h;
        *reinterpret_cast<float4*>(lo + row * LDT + kq * 4) = l;
    }
}
// B transpose: W row-major [K, ldb]; slice rows k0..k0+31, cols nb..nb+127 -> [n][k]
__device__ __forceinline__ void ldg_tileB(const float* __restrict__ W, int ldb, int nb,
                                          int k0, int tid, float4* r)
{
#pragma unroll
    for (int i = 0; i < 4; ++i) {
        const int idx = tid + i * 256;
        const int n  = idx & 127;
        const int kg = (idx >> 7) * 4;
        const float* src = W + (size_t)(k0 + kg) * ldb + nb + n;
        r[i].x = src[0];
        r[i].y = src[(size_t)ldb];
        r[i].z = src[(size_t)2 * ldb];
        r[i].w = src[(size_t)3 * ldb];
    }
}
__device__ __forceinline__ void sts_tileB_split(float* __restrict__ hi, float* __restrict__ lo,
                                                int tid, const float4* r)
{
#pragma unroll
    for (int i = 0; i < 4; ++i) {
        const int idx = tid + i * 256;
        const int n  = idx & 127;
        const int kg = (idx >> 7) * 4;
        float4 h, l;
        h.x = tf_round(r[i].x); l.x = r[i].x - h.x;
        h.y = tf_round(r[i].y); l.y = r[i].y - h.y;
        h.z = tf_round(r[i].z); l.z = r[i].z - h.z;
        h.w = tf_round(r[i].w); l.w = r[i].w - h.w;
        *reinterpret_cast<float4*>(hi + n * LDT + kg) = h;
        *reinterpret_cast<float4*>(lo + n * LDT + kg) = l;
    }
}
__device__ __forceinline__ void sts_tileB_raw(float* __restrict__ dst, int tid, const float4* r)
{
#pragma unroll
    for (int i = 0; i < 4; ++i) {
        const int idx = tid + i * 256;
        const int n  = idx & 127;
        const int kg = (idx >> 7) * 4;
        *reinterpret_cast<float4*>(dst + n * LDT + kg) = r[i];
    }
}

// ---- fragment loads (k-lane permuted pairs: lane tig <- col 2tig, lane tig+4 <- col 2tig+1)
// Valid because A and B use the SAME permutation -> dot product unchanged.
__device__ __forceinline__ void ldA_p(const float* __restrict__ s, int row0, int kc,
                                      int gid, int tig, uint32_t* a)
{
    float2 v0 = *reinterpret_cast<const float2*>(s + (row0 + gid)     * LDT + kc + 2 * tig);
    float2 v1 = *reinterpret_cast<const float2*>(s + (row0 + gid + 8) * LDT + kc + 2 * tig);
    a[0] = __float_as_uint(v0.x); a[2] = __float_as_uint(v0.y);
    a[1] = __float_as_uint(v1.x); a[3] = __float_as_uint(v1.y);
}
__device__ __forceinline__ void ldB_p(const float* __restrict__ s, int n0, int kc,
                                      int gid, int tig, uint32_t* b)
{
    float2 v = *reinterpret_cast<const float2*>(s + (n0 + gid) * LDT + kc + 2 * tig);
    b[0] = __float_as_uint(v.x); b[1] = __float_as_uint(v.y);
}

// ---- 128x128x32 chunk variants ----
__device__ __forceinline__ void chunk_rn(const float* __restrict__ cA, const float* __restrict__ cB,
                                         int wm, int wn, int gid, int tig, float (&acc)[4][4][4])
{
#pragma unroll
    for (int ks = 0; ks < 4; ++ks) {
        const int kc = ks * 8;
        uint32_t af[4][4], bf[4][2];
#pragma unroll
        for (int mt = 0; mt < 4; ++mt) ldA_p(cA, wm + mt * 16, kc, gid, tig, af[mt]);
#pragma unroll
        for (int nl = 0; nl < 4; ++nl) ldB_p(cB, wn + nl * 8, kc, gid, tig, bf[nl]);
#pragma unroll
        for (int mt = 0; mt < 4; ++mt)
#pragma unroll
            for (int nl = 0; nl < 4; ++nl)
                mma_tf32(acc[mt][nl], af[mt], bf[nl]);
    }
}
__device__ __forceinline__ void chunk_x3(const float* __restrict__ cAh, const float* __restrict__ cAl,
                                         const float* __restrict__ cBh, const float* __restrict__ cBl,
                                         int wm, int wn, int gid, int tig, float (&acc)[4][4][4])
{
#pragma unroll
    for (int ks = 0; ks < 4; ++ks) {
        const int kc = ks * 8;
        uint32_t ah[4][4], al[4][4], bh[4][2], bl[4][2];
#pragma unroll
        for (int mt = 0; mt < 4; ++mt) {
            ldA_p(cAh, wm + mt * 16, kc, gid, tig, ah[mt]);
            ldA_p(cAl, wm + mt * 16, kc, gid, tig, al[mt]);
        }
#pragma unroll
        for (int nl = 0; nl < 4; ++nl) {
            ldB_p(cBh, wn + nl * 8, kc, gid, tig, bh[nl]);
            ldB_p(cBl, wn + nl * 8, kc, gid, tig, bl[nl]);
        }
#pragma unroll
        for (int mt = 0; mt < 4; ++mt)
#pragma unroll
            for (int nl = 0; nl < 4; ++nl) {
                mma_tf32(acc[mt][nl], al[mt], bh[nl]);
                mma_tf32(acc[mt][nl], ah[mt], bl[nl]);
                mma_tf32(acc[mt][nl], ah[mt], bh[nl]);
            }
    }
}
__device__ __forceinline__ void chunk_x2(const float* __restrict__ cAh, const float* __restrict__ cAl,
                                         const float* __restrict__ cBh,
                                         int wm, int wn, int gid, int tig, float (&acc)[4][4][4])
{
#pragma unroll
    for (int ks = 0; ks < 4; ++ks) {
        const int kc = ks * 8;
        uint32_t ah[4][4], al[4][4], bh[4][2];
#pragma unroll
        for (int mt = 0; mt < 4; ++mt) {
            ldA_p(cAh, wm + mt * 16, kc, gid, tig, ah[mt]);
            ldA_p(cAl, wm + mt * 16, kc, gid, tig, al[mt]);
        }
#pragma unroll
        for (int nl = 0; nl < 4; ++nl) ldB_p(cBh, wn + nl * 8, kc, gid, tig, bh[nl]);
#pragma unroll
        for (int mt = 0; mt < 4; ++mt)
#pragma unroll
            for (int nl = 0; nl < 4; ++nl) {
                mma_tf32(acc[mt][nl], al[mt], bh[nl]);
                mma_tf32(acc[mt][nl], ah[mt], bh[nl]);
            }
    }
}

// ---------------------------------------------------------------------------
// Fused scores: operands pre-rounded -> pure LDS+HMMA mainloop.
// grid (32, 32, 4). smem 8 tiles = 163840 B.
// ---------------------------------------------------------------------------
__global__ void __launch_bounds__(NTHREADS)
scores_tc_kernel(const float* __restrict__ Qm, const float* __restrict__ Km,
                 const float* __restrict__ tQm, const float* __restrict__ tKm,
                 float* __restrict__ S)
{
    extern __shared__ float sm[];
    float* SA1 = sm;
    float* SB1 = sm + 2 * TILE_F;
    float* SA2 = sm + 4 * TILE_F;
    float* SB2 = sm + 6 * TILE_F;
    const uint32_t a1b = (uint32_t)__cvta_generic_to_shared(SA1);
    const uint32_t b1b = (uint32_t)__cvta_generic_to_shared(SB1);
    const uint32_t a2b = (uint32_t)__cvta_generic_to_shared(SA2);
    const uint32_t b2b = (uint32_t)__cvta_generic_to_shared(SB2);

    const int tid  = threadIdx.x;
    const int wid  = tid >> 5;
    const int lane = tid & 31;
    const int gid  = lane >> 2;
    const int tig  = lane & 3;
    const int wm   = (wid & 1) * 64;
    const int wn   = (wid >> 1) * 32;

    const int b  = blockIdx.z;
    const int mb = blockIdx.y * 128;
    const int nb = blockIdx.x * 128;
    const float* A1 = Qm  + (size_t)b * NSEQ * D + (size_t)mb * D;
    const float* B1 = Km  + (size_t)b * NSEQ * D + (size_t)nb * D;
    const float* A2 = tQm + (size_t)b * NSEQ * D + (size_t)mb * D;
    const float* B2 = tKm + (size_t)b * NSEQ * D + (size_t)nb * D;

    float acc1[4][4][4] = {};
    float acc2[4][4][4] = {};

    const int nt = D / KC; // 8
    const uint32_t bufB = (uint32_t)TILE_F * 4;

    tile_cp(A1, D, 0, a1b, tid);
    tile_cp(B1, D, 0, b1b, tid);
    tile_cp(A2, D, 0, a2b, tid);
    tile_cp(B2, D, 0, b2b, tid);
    cp_commit();

    for (int t = 0; t < nt; ++t) {
        const int cur = t & 1;
        if (t + 1 < nt) {
            const int k0 = (t + 1) * KC;
            const uint32_t off = (uint32_t)((t + 1) & 1) * bufB;
            tile_cp(A1, D, k0, a1b + off, tid);
            tile_cp(B1, D, k0, b1b + off, tid);
            tile_cp(A2, D, k0, a2b + off, tid);
            tile_cp(B2, D, k0, b2b + off, tid);
            cp_commit();
            cp_wait1();
        } else {
            cp_wait0();
        }
        __syncthreads();

        chunk_rn(SA1 + cur * TILE_F, SB1 + cur * TILE_F, wm, wn, gid, tig, acc1);
        chunk_rn(SA2 + cur * TILE_F, SB2 + cur * TILE_F, wm, wn, gid, tig, acc2);
        __syncthreads();
    }

    float* Sb = S + (size_t)b * NSEQ * NSEQ;
#pragma unroll
    for (int mt = 0; mt < 4; ++mt) {
        const int row = mb + wm + mt * 16 + gid;
#pragma unroll
        for (int nl = 0; nl < 4; ++nl) {
            const int col = nb + wn + nl * 8 + tig * 2;
            const float* a1 = acc1[mt][nl];
            const float* a2 = acc2[mt][nl];
            float2 v0 = make_float2(a1[0] * (a2[0] + 1.f) * 0.03125f,
                                    a1[1] * (a2[1] + 1.f) * 0.03125f);
            float2 v1 = make_float2(a1[2] * (a2[2] + 1.f) * 0.03125f,
                                    a1[3] * (a2[3] + 1.f) * 0.03125f);
            *reinterpret_cast<float2*>(Sb + (size_t)row * NSEQ + col)       = v0;
            *reinterpret_cast<float2*>(Sb + (size_t)(row + 8) * NSEQ + col) = v1;
        }
    }
}

// ---------------------------------------------------------------------------
// Projection (x3, pre-split smem): Out=X@W+bias with full/rounded/tanh outputs
// grid (2, 128). smem 8 tiles = 163840 B.
// ---------------------------------------------------------------------------
__global__ void __launch_bounds__(NTHREADS)
proj_tc_kernel(const float* __restrict__ X, const float* __restrict__ W,
               const float* __restrict__ bias,
               float* __restrict__ OutF, float* __restrict__ OutR,
               float* __restrict__ TOutR)
{
    extern __shared__ float sm[];
    float* Ah = sm;
    float* Al = sm + 2 * TILE_F;
    float* Bh = sm + 4 * TILE_F;
    float* Bl = sm + 6 * TILE_F;

    const int tid  = threadIdx.x;
    const int wid  = tid >> 5;
    const int lane = tid & 31;
    const int gid  = lane >> 2;
    const int tig  = lane & 3;
    const int wm   = (wid & 1) * 64;
    const int wn   = (wid >> 1) * 32;

    const int mb = blockIdx.y * 128;
    const int nb = blockIdx.x * 128;
    const float* A = X + (size_t)mb * D;

    float acc[4][4][4] = {};
    const int nt = D / KC; // 8

    float4 rA[4], rB[4];
    ldg_tileA(A, D, 0, tid, rA);
    ldg_tileB(W, D, nb, 0, tid, rB);
    sts_tileA_split(Ah, Al, tid, rA);
    sts_tileB_split(Bh, Bl, tid, rB);
    __syncthreads();

    for (int t = 0; t < nt; ++t) {
        const int cur = t & 1;
        const int nxt = cur ^ 1;
        if (t + 1 < nt) {
            ldg_tileA(A, D, (t + 1) * KC, tid, rA);
            ldg_tileB(W, D, nb, (t + 1) * KC, tid, rB);
        }
        chunk_x3(Ah + cur * TILE_F, Al + cur * TILE_F,
                 Bh + cur * TILE_F, Bl + cur * TILE_F, wm, wn, gid, tig, acc);
        if (t + 1 < nt) {
            sts_tileA_split(Ah + nxt * TILE_F, Al + nxt * TILE_F, tid, rA);
            sts_tileB_split(Bh + nxt * TILE_F, Bl + nxt * TILE_F, tid, rB);
        }
        __syncthreads();
    }

#pragma unroll
    for (int mt = 0; mt < 4; ++mt) {
        const int row = mb + wm + mt * 16 + gid;
#pragma unroll
        for (int nl = 0; nl < 4; ++nl) {
            const int col = nb + wn + nl * 8 + tig * 2;
            const float* a = acc[mt][nl];
            const float b0 = bias[col], b1 = bias[col + 1];
            float v00 = a[0] + b0, v01 = a[1] + b1;
            float v10 = a[2] + b0, v11 = a[3] + b1;
            if (OutF) {
                *reinterpret_cast<float2*>(OutF + (size_t)row * D + col)       = make_float2(v00, v01);
                *reinterpret_cast<float2*>(OutF + (size_t)(row + 8) * D + col) = make_float2(v10, v11);
            }
            if (OutR) {
                *reinterpret_cast<float2*>(OutR + (size_t)row * D + col)       = make_float2(tf_round(v00), tf_round(v01));
                *reinterpret_cast<float2*>(OutR + (size_t)(row + 8) * D + col) = make_float2(tf_round(v10), tf_round(v11));
            }
            if (TOutR) {
                *reinterpret_cast<float2*>(TOutR + (size_t)row * D + col)       = make_float2(tf_round(tanhf(v00)), tf_round(tanhf(v01)));
                *reinterpret_cast<float2*>(TOutR + (size_t)(row + 8) * D + col) = make_float2(tf_round(tanhf(v10)), tf_round(tanhf(v11)));
            }
        }
    }
}

// ---------------------------------------------------------------------------
// PV (x2): Qhat = attn @ Vr. attn split hi/lo at STS; Vr pre-rounded.
// grid (2, 32, 4). smem 6 tiles = 122880 B.
// ---------------------------------------------------------------------------
__global__ void __launch_bounds__(NTHREADS)
pv_tc_kernel(const float* __restrict__ attn, const float* __restrict__ Vr,
             float* __restrict__ Qhat)
{
    extern __shared__ float sm[];
    float* Ah = sm;
    float* Al = sm + 2 * TILE_F;
    float* Bh = sm + 4 * TILE_F;

    const int tid  = threadIdx.x;
    const int wid  = tid >> 5;
    const int lane = tid & 31;
    const int gid  = lane >> 2;
    const int tig  = lane & 3;
    const int wm   = (wid & 1) * 64;
    const int wn   = (wid >> 1) * 32;

    const int b  = blockIdx.z;
    const int mb = blockIdx.y * 128;
    const int nb = blockIdx.x * 128;
    const float* Ab = attn + (size_t)b * NSEQ * NSEQ + (size_t)mb * NSEQ;
    const float* Vb = Vr + (size_t)b * NSEQ * D;

    float acc[4][4][4] = {};
    const int nt = NSEQ / KC; // 128

    float4 rA[4], rB[4];
    ldg_tileA(Ab, NSEQ, 0, tid, rA);
    ldg_tileB(Vb, D, nb, 0, tid, rB);
    sts_tileA_split(Ah, Al, tid, rA);
    sts_tileB_raw(Bh, tid, rB);
    __syncthreads();

    for (int t = 0; t < nt; ++t) {
        const int cur = t & 1;
        const int nxt = cur ^ 1;
        if (t + 1 < nt) {
            ldg_tileA(Ab, NSEQ, (t + 1) * KC, tid, rA);
            ldg_tileB(Vb, D, nb, (t + 1) * KC, tid, rB);
        }
        chunk_x2(Ah + cur * TILE_F, Al + cur * TILE_F, Bh + cur * TILE_F,
                 wm, wn, gid, tig, acc);
        if (t + 1 < nt) {
            sts_tileA_split(Ah + nxt * TILE_F, Al + nxt * TILE_F, tid, rA);
            sts_tileB_raw(Bh + nxt * TILE_F, tid, rB);
        }
        __syncthreads();
    }

    float* Qb = Qhat + (size_t)b * NSEQ * D;
#pragma unroll
    for (int mt = 0; mt < 4; ++mt) {
        const int row = mb + wm + mt * 16 + gid;
#pragma unroll
        for (int nl = 0; nl < 4; ++nl) {
            const int col = nb + wn + nl * 8 + tig * 2;
            const float* a = acc[mt][nl];
            *reinterpret_cast<float2*>(Qb + (size_t)row * D + col)       = make_float2(a[0], a[1]);
            *reinterpret_cast<float2*>(Qb + (size_t)(row + 8) * D + col) = make_float2(a[2], a[3]);
        }
    }
}

// ---------------------------------------------------------------------------
// Dual gate (x3): OutA = relu(X@Wa+ba), OutB = relu(X@Wb+bb).
// A double-buffered split; B hi/lo single-buffered. grid (1, 128).
// smem 8 tiles = 163840 B. JIT ldg (no reg prefetch; nt=8, latency negligible).
// ---------------------------------------------------------------------------
__global__ void __launch_bounds__(NTHREADS)
dualgate_tc_kernel(const float* __restrict__ X,
                   const float* __restrict__ Wa, const float* __restrict__ ba,
                   const float* __restrict__ Wb, const float* __restrict__ bb,
                   float* __restrict__ OutA, float* __restrict__ OutB)
{
    extern __shared__ float sm[];
    float* Ah  = sm;                    // 2 buffers
    float* Al  = sm + 2 * TILE_F;       // 2 buffers
    float* Bha = sm + 4 * TILE_F;       // single
    float* Bla = sm + 5 * TILE_F;
    float* Bhb = sm + 6 * TILE_F;
    float* Blb = sm + 7 * TILE_F;

    const int tid  = threadIdx.x;
    const int wid  = tid >> 5;
    const int lane = tid & 31;
    const int gid  = lane >> 2;
    const int tig  = lane & 3;
    const int wm   = (wid & 1) * 64;
    const int wn   = (wid >> 1) * 32;

    const int mb = blockIdx.y * 128;
    const float* A = X + (size_t)mb * D;

    float accA[4][4][4] = {};
    float accB[4][4][4] = {};
    const int nt = D / KC; // 8

    {
        float4 r[4];
        ldg_tileA(A, D, 0, tid, r);
        sts_tileA_split(Ah, Al, tid, r);
        ldg_tileB(Wa, OUTC, 0, 0, tid, r);
        sts_tileB_split(Bha, Bla, tid, r);
        ldg_tileB(Wb, OUTC, 0, 0, tid, r);
        sts_tileB_split(Bhb, Blb, tid, r);
    }
    __syncthreads();

    for (int t = 0; t < nt; ++t) {
        const int cur = t & 1;
        const int nxt = cur ^ 1;
        chunk_x3(Ah + cur * TILE_F, Al + cur * TILE_F, Bha, Bla, wm, wn, gid, tig, accA);
        chunk_x3(Ah + cur * TILE_F, Al + cur * TILE_F, Bhb, Blb, wm, wn, gid, tig, accB);
        __syncthreads();     // everyone done with B tiles (and A cur)
        if (t + 1 < nt) {
            float4 r[4];
            const int k0 = (t + 1) * KC;
            ldg_tileA(A, D, k0, tid, r);
            sts_tileA_split(Ah + nxt * TILE_F, Al + nxt * TILE_F, tid, r);
            ldg_tileB(Wa, OUTC, 0, k0, tid, r);
            sts_tileB_split(Bha, Bla, tid, r);
            ldg_tileB(Wb, OUTC, 0, k0, tid, r);
            sts_tileB_split(Bhb, Blb, tid, r);
        }
        __syncthreads();
    }

#pragma unroll
    for (int mt = 0; mt < 4; ++mt) {
        const int row = mb + wm + mt * 16 + gid;
#pragma unroll
        for (int nl = 0; nl < 4; ++nl) {
            const int col = wn + nl * 8 + tig * 2;
            const float* a = accA[mt][nl];
            const float* c = accB[mt][nl];
            float a0 = ba[col], a1 = ba[col + 1];
            float c0 = bb[col], c1 = bb[col + 1];
            *reinterpret_cast<float2*>(OutA + (size_t)row * OUTC + col) =
                make_float2(relu_f(a[0] + a0), relu_f(a[1] + a1));
            *reinterpret_cast<float2*>(OutA + (size_t)(row + 8) * OUTC + col) =
                make_float2(relu_f(a[2] + a0), relu_f(a[3] + a1));
            *reinterpret_cast<float2*>(OutB + (size_t)row * OUTC + col) =
                make_float2(relu_f(c[0] + c0), relu_f(c[1] + c1));
            *reinterpret_cast<float2*>(OutB + (size_t)(row + 8) * OUTC + col) =
                make_float2(relu_f(c[2] + c0), relu_f(c[3] + c1));
        }
    }
}

// ---------------------------------------------------------------------------
// Final (x3): out1 = Qf + relu(GE @ Wc + bc). grid (1, 128).
// A double split, B hi/lo single. smem 6 tiles = 122880 B.
// ---------------------------------------------------------------------------
__global__ void __launch_bounds__(NTHREADS)
final_tc_kernel(const float* __restrict__ GE, const float* __restrict__ Wc,
                const float* __restrict__ bc, const float* __restrict__ Qf,
                float* __restrict__ Out)
{
    extern __shared__ float sm[];
    float* Ah = sm;                 // 2 buffers
    float* Al = sm + 2 * TILE_F;    // 2 buffers
    float* Bh = sm + 4 * TILE_F;    // single
    float* Bl = sm + 5 * TILE_F;

    const int tid  = threadIdx.x;
    const int wid  = tid >> 5;
    const int lane = tid & 31;
    const int gid  = lane >> 2;
    const int tig  = lane & 3;
    const int wm   = (wid & 1) * 64;
    const int wn   = (wid >> 1) * 32;

    const int mb = blockIdx.y * 128;
    const float* A = GE + (size_t)mb * OUTC;

    float acc[4][4][4] = {};
    const int nt = OUTC / KC; // 4

    {
        float4 r[4];
        ldg_tileA(A, OUTC, 0, tid, r);
        sts_tileA_split(Ah, Al, tid, r);
        ldg_tileB(Wc, OUTC, 0, 0, tid, r);
        sts_tileB_split(Bh, Bl, tid, r);
    }
    __syncthreads();

    for (int t = 0; t < nt; ++t) {
        const int cur = t & 1;
        const int nxt = cur ^ 1;
        chunk_x3(Ah + cur * TILE_F, Al + cur * TILE_F, Bh, Bl, wm, wn, gid, tig, acc);
        __syncthreads();
        if (t + 1 < nt) {
            float4 r[4];
            const int k0 = (t + 1) * KC;
            ldg_tileA(A, OUTC, k0, tid, r);
            sts_tileA_split(Ah + nxt * TILE_F, Al + nxt * TILE_F, tid, r);
            ldg_tileB(Wc, OUTC, 0, k0, tid, r);
            sts_tileB_split(Bh, Bl, tid, r);
        }
        __syncthreads();
    }

#pragma unroll
    for (int mt = 0; mt < 4; ++mt) {
        const int row = mb + wm + mt * 16 + gid;
#pragma unroll
        for (int nl = 0; nl < 4; ++nl) {
            const int col = wn + nl * 8 + tig * 2;
            const float* a = acc[mt][nl];
            const float b0 = bc[col], b1 = bc[col + 1];
            const float* q0 = Qf + (size_t)row * OUTC + col;
            const float* q1 = Qf + (size_t)(row + 8) * OUTC + col;
            *reinterpret_cast<float2*>(Out + (size_t)row * OUTC + col) =
                make_float2(q0[0] + relu_f(a[0] + b0), q0[1] + relu_f(a[1] + b1));
            *reinterpret_cast<float2*>(Out + (size_t)(row + 8) * OUTC + col) =
                make_float2(q1[0] + relu_f(a[2] + b0), q1[1] + relu_f(a[3] + b1));
        }
    }
}

// ---------------------------------------------------------------------------
// Softmax (float4): attn = softmax_row(S). one CTA per row. grid 16384
// ---------------------------------------------------------------------------
__global__ void __launch_bounds__(NTHREADS)
softmax_kernel(const float* __restrict__ S, float* __restrict__ attn)
{
    __shared__ float4 rowbuf[NSEQ / 4];
    __shared__ float red[8];
    __shared__ float bcast;
    const size_t r = blockIdx.x;
    const float4* ps = reinterpret_cast<const float4*>(S + r * NSEQ);
    float4* po = reinterpret_cast<float4*>(attn + r * NSEQ);
    const int tid = threadIdx.x;

    float m = -1e30f;
    for (int i = tid; i < NSEQ / 4; i += NTHREADS) {
        float4 v = ps[i];
        rowbuf[i] = v;
        m = fmaxf(fmaxf(fmaxf(m, v.x), fmaxf(v.y, v.z)), v.w);
    }
#pragma unroll
    for (int off = 16; off; off >>= 1) m = fmaxf(m, __shfl_xor_sync(0xffffffffu, m, off));
    if ((tid & 31) == 0) red[tid >> 5] = m;
    __syncthreads();
    if (tid < 8) {
        float mm = red[tid];
#pragma unroll
        for (int off = 4; off; off >>= 1) mm = fmaxf(mm, __shfl_xor_sync(0xffu, mm, off));
        if (tid == 0) bcast = mm;
    }
    __syncthreads();
    const float M = bcast;

    float s = 0.f;
    for (int i = tid; i < NSEQ / 4; i += NTHREADS) {
        float4 v = rowbuf[i];
        v.x = __expf(v.x - M); v.y = __expf(v.y - M);
        v.z = __expf(v.z - M); v.w = __expf(v.w - M);
        rowbuf[i] = v;
        s += v.x + v.y + v.z + v.w;
    }
#pragma unroll
    for (int off = 16; off; off >>= 1) s += __shfl_xor_sync(0xffffffffu, s, off);
    __syncthreads();
    if ((tid & 31) == 0) red[tid >> 5] = s;
    __syncthreads();
    if (tid < 8) {
        float ss = red[tid];
#pragma unroll
        for (int off = 4; off; off >>= 1) ss += __shfl_xor_sync(0xffu, ss, off);
        if (tid == 0) bcast = 1.0f / ss;
    }
    __syncthreads();
    const float inv = bcast;
    for (int i = tid; i < NSEQ / 4; i += NTHREADS) {
        float4 v = rowbuf[i];
        v.x *= inv; v.y *= inv; v.z *= inv; v.w *= inv;
        po[i] = v;
    }
}

// ---------------------------------------------------------------------------
// LayerNorm gate: GE = LN(relu(T1+T2)) * LN(relu(T3)). grid 16384, 128 thr
// ---------------------------------------------------------------------------
__global__ void __launch_bounds__(OUTC)
lngate_kernel(const float* __restrict__ T1, const float* __restrict__ T2,
              const float* __restrict__ T3,
              const float* __restrict__ gg, const float* __restrict__ gb,
              const float* __restrict__ eg, const float* __restrict__ eb,
              float* __restrict__ GE)
{
    __shared__ float2 red[4];
    const size_t r = blockIdx.x;
    const int c = threadIdx.x;

    float a = relu_f(T1[r * OUTC + c] + T2[r * OUTC + c]);
    float2 v = make_float2(a, a * a);
#pragma unroll
    for (int off = 16; off; off >>= 1) {
        v.x += __shfl_xor_sync(0xffffffffu, v.x, off);
        v.y += __shfl_xor_sync(0xffffffffu, v.y, off);
    }
    if ((c & 31) == 0) red[c >> 5] = v;
    __syncthreads();
    float sx = red[0].x + red[1].x + red[2].x + red[3].x;
    float sy = red[0].y + red[1].y + red[2].y + red[3].y;
    float mu  = sx * (1.f / OUTC);
    float var = sy * (1.f / OUTC) - mu * mu;
    float g = (a - mu) * rsqrtf(var + 1e-5f) * gg[c] + gb[c];

    float e0 = relu_f(T3[r * OUTC + c]);
    __syncthreads();
    v = make_float2(e0, e0 * e0);
#pragma unroll
    for (int off = 16; off; off >>= 1) {
        v.x += __shfl_xor_sync(0xffffffffu, v.x, off);
        v.y += __shfl_xor_sync(0xffffffffu, v.y, off);
    }
    if ((c & 31) == 0) red[c >> 5] = v;
    __syncthreads();
    sx = red[0].x + red[1].x + red[2].x + red[3].x;
    sy = red[0].y + red[1].y + red[2].y + red[3].y;
    float mu2  = sx * (1.f / OUTC);
    float var2 = sy * (1.f / OUTC) - mu2 * mu2;
    float e = (e0 - mu2) * rsqrtf(var2 + 1e-5f) * eg[c] + eb[c];

    GE[r * OUTC + c] = g * e;
}

// ---------------------------------------------------------------------------
// Launch
// ---------------------------------------------------------------------------
extern "C" void kernel_launch(void* const* d_in, const int* in_sizes, int n_in,
                              void* d_out, int out_size)
{
    const float* x1  = (const float*)d_in[0];
    const float* x2  = (const float*)d_in[1];
    const float* W_q = (const float*)d_in[2];  const float* b_q = (const float*)d_in[3];
    const float* W_k = (const float*)d_in[4];  const float* b_k = (const float*)d_in[5];
    const float* W_v = (const float*)d_in[6];  const float* b_v = (const float*)d_in[7];
    const float* W1  = (const float*)d_in[8];  const float* b1  = (const float*)d_in[9];
    const float* W2  = (const float*)d_in[10]; const float* b2  = (const float*)d_in[11];
    const float* W3  = (const float*)d_in[12]; const float* b3  = (const float*)d_in[13];
    const float* gg  = (const float*)d_in[14]; const float* gb  = (const float*)d_in[15];
    const float* eg  = (const float*)d_in[16]; const float* eb  = (const float*)d_in[17];
    const float* W_c = (const float*)d_in[18]; const float* b_c = (const float*)d_in[19];
    const float* W_f = (const float*)d_in[20]; const float* b_f = (const float*)d_in[21];

    float* out1 = (float*)d_out;
    float* attn = out1 + OUT1_ELEMS;

    void* p;
    cudaGetSymbolAddress(&p, g_Q);    float* Q    = (float*)p;
    cudaGetSymbolAddress(&p, g_Qr);   float* Qr   = (float*)p;
    cudaGetSymbolAddress(&p, g_Kr);   float* Kr   = (float*)p;
    cudaGetSymbolAddress(&p, g_Vr);   float* Vr   = (float*)p;
    cudaGetSymbolAddress(&p, g_tQ);   float* tQ   = (float*)p;
    cudaGetSymbolAddress(&p, g_tK);   float* tK   = (float*)p;
    cudaGetSymbolAddress(&p, g_S);    float* S    = (float*)p;
    cudaGetSymbolAddress(&p, g_Qhat); float* Qhat = (float*)p;
    cudaGetSymbolAddress(&p, g_T1);   float* T1   = (float*)p;
    cudaGetSymbolAddress(&p, g_T2);   float* T2   = (float*)p;
    cudaGetSymbolAddress(&p, g_T3);   float* T3   = (float*)p;
    cudaGetSymbolAddress(&p, g_Qf);   float* Qf   = (float*)p;
    cudaGetSymbolAddress(&p, g_GE);   float* GE   = (float*)p;

    const int smem8 = 8 * TILE_F * (int)sizeof(float);  // 163840
    const int smem6 = 6 * TILE_F * (int)sizeof(float);  // 122880
    cudaFuncSetAttribute(scores_tc_kernel,   cudaFuncAttributeMaxDynamicSharedMemorySize, smem8);
    cudaFuncSetAttribute(proj_tc_kernel,     cudaFuncAttributeMaxDynamicSharedMemorySize, smem8);
    cudaFuncSetAttribute(pv_tc_kernel,       cudaFuncAttributeMaxDynamicSharedMemorySize, smem6);
    cudaFuncSetAttribute(dualgate_tc_kernel, cudaFuncAttributeMaxDynamicSharedMemorySize, smem8);
    cudaFuncSetAttribute(final_tc_kernel,    cudaFuncAttributeMaxDynamicSharedMemorySize, smem6);

    dim3 blk(NTHREADS);

    // Projections (x3): Q (full + rounded + tanh), K (rounded + tanh), V (rounded)
    proj_tc_kernel<<<dim3(2, 128), blk, smem8>>>(x2, W_q, b_q, Q,       Qr, tQ);
    proj_tc_kernel<<<dim3(2, 128), blk, smem8>>>(x1, W_k, b_k, nullptr, Kr, tK);
    proj_tc_kernel<<<dim3(2, 128), blk, smem8>>>(x1, W_v, b_v, nullptr, Vr, nullptr);

    // Fused score GEMMs (pre-rounded operands) -> combined pre-softmax scores
    scores_tc_kernel<<<dim3(32, 32, 4), blk, smem8>>>(Qr, Kr, tQ, tK, S);

    // Softmax -> attn (output)
    softmax_kernel<<<BATCH * NSEQ, blk>>>(S, attn);

    // Q_hat = attn @ V (x2: attn hi/lo x V rounded)
    pv_tc_kernel<<<dim3(2, 32, 4), blk, smem6>>>(attn, Vr, Qhat);

    // Gate projections (shared-A dual GEMMs, x3)
    dualgate_tc_kernel<<<dim3(1, 128), blk, smem8>>>(Q,    W1, b1, W_f, b_f, T1, Qf);
    dualgate_tc_kernel<<<dim3(1, 128), blk, smem8>>>(Qhat, W2, b2, W3,  b3,  T2, T3);

    // LayerNorms + gate product
    lngate_kernel<<<BATCH * NSEQ, OUTC>>>(T1, T2, T3, gg, gb, eg, eb, GE);

    // out1 = Qf + relu(GE @ Wc + bc) (x3)
    final_tc_kernel<<<dim3(1, 128), blk, smem6>>>(GE, W_c, b_c, Qf, out1);
}

// round 7
// speedup vs baseline: 1.3791x; 1.0057x over previous
#include <cuda_runtime.h>
#include <math.h>
#include <stdint.h>

// ---------------------------------------------------------------------------
// PreGatingContextualAttentionGate — round 7
// R6 + : scores/PV at 512 threads (16 warps, 4/SMSP, warp tile 32x32) and
// single-__syncthreads scores mainloop. Numerics bit-identical to R6.
// B=4, N=4096, D=DK=256, OUT=128
// d_out layout: [ out1 = Qf + C : 4*4096*128 f32 ][ attn : 4*4096*4096 f32 ]
// ---------------------------------------------------------------------------

static constexpr int    BATCH = 4;
static constexpr int    NSEQ  = 4096;
static constexpr int    D     = 256;
static constexpr int    OUTC  = 128;
static constexpr size_t ROWS  = (size_t)BATCH * NSEQ;             // 16384
static constexpr size_t QK_ELEMS   = ROWS * D;                    // 4 M
static constexpr size_t S_ELEMS    = (size_t)BATCH * NSEQ * NSEQ; // 67 M
static constexpr size_t OUT1_ELEMS = ROWS * OUTC;                 // 2 M

static constexpr int KC     = 32;            // k-chunk
static constexpr int LDT    = 40;            // padded smem row stride (floats)
static constexpr int TILE_F = 128 * LDT;     // floats per 128x32 tile buffer

// Scratch (static device arrays — the sanctioned workaround)
__device__ float g_Q  [QK_ELEMS];
__device__ float g_Qr [QK_ELEMS];
__device__ float g_Kr [QK_ELEMS];
__device__ float g_Vr [QK_ELEMS];
__device__ float g_tQ [QK_ELEMS];
__device__ float g_tK [QK_ELEMS];
__device__ float g_S  [S_ELEMS];
__device__ float g_Qhat[QK_ELEMS];
__device__ float g_T1 [OUT1_ELEMS];
__device__ float g_T2 [OUT1_ELEMS];
__device__ float g_T3 [OUT1_ELEMS];
__device__ float g_Qf [OUT1_ELEMS];
__device__ float g_GE [OUT1_ELEMS];

__device__ __forceinline__ float relu_f(float x) { return x > 0.f ? x : 0.f; }

// ---------------------------------------------------------------------------
// tf32 helpers
// ---------------------------------------------------------------------------
__device__ __forceinline__ uint32_t f2tf(float f) {
    uint32_t u;
    asm("cvt.rna.tf32.f32 %0, %1;" : "=r"(u) : "f"(f));
    return u;
}
__device__ __forceinline__ float tf_round(float f) { return __uint_as_float(f2tf(f)); }

__device__ __forceinline__ void mma_tf32(float* d, const uint32_t* a, const uint32_t* b) {
    asm volatile(
        "mma.sync.aligned.m16n8k8.row.col.f32.tf32.tf32.f32 "
        "{%0,%1,%2,%3}, {%4,%5,%6,%7}, {%8,%9}, {%0,%1,%2,%3};"
        : "+f"(d[0]), "+f"(d[1]), "+f"(d[2]), "+f"(d[3])
        : "r"(a[0]), "r"(a[1]), "r"(a[2]), "r"(a[3]), "r"(b[0]), "r"(b[1]));
}

__device__ __forceinline__ void cp16(uint32_t saddr, const void* g) {
    asm volatile("cp.async.cg.shared.global [%0], [%1], 16;" :: "r"(saddr), "l"(g));
}
__device__ __forceinline__ void cp_commit() { asm volatile("cp.async.commit_group;"); }
__device__ __forceinline__ void cp_wait0()  { asm volatile("cp.async.wait_group 0;"); }

// cp.async one 128x32 row-major tile (1024 x 16B chunks) across NT threads.
template<int NT>
__device__ __forceinline__ void tile_cp(const float* __restrict__ g, int ldg, int k0,
                                        uint32_t sbase, int tid)
{
#pragma unroll
    for (int i = 0; i < 1024 / NT; ++i) {
        const int fid = tid + i * NT;
        const int row = fid >> 3;
        const int kq  = fid & 7;
        cp16(sbase + (uint32_t)(row * LDT + kq * 4) * 4,
             g + (size_t)row * ldg + k0 + kq * 4);
    }
}

// ---- LDG staging (A row-major tile; B transpose tile) ----
template<int NT>
__device__ __forceinline__ void ldg_tileA(const float* __restrict__ A, int lda, int k0,
                                          int tid, float4* r)
{
#pragma unroll
    for (int i = 0; i < 1024 / NT; ++i) {
        const int fid = tid + i * NT;
        const int row = fid >> 3;
        const int kq  = fid & 7;
        r[i] = *reinterpret_cast<const float4*>(A + (size_t)row * lda + k0 + kq * 4);
    }
}
template<int NT>
__device__ __forceinline__ void sts_tileA_split(float* __restrict__ hi, float* __restrict__ lo,
                                                int tid, const float4* r)
{
#pragma unroll
    for (int i = 0; i < 1024 / NT; ++i) {
        const int fid = tid + i * NT;
        const int row = fid >> 3;
        const int kq  = fid & 7;
        float4 h, l;
        h.x = tf_round(r[i].x); l.x = r[i].x - h.x;
        h.y = tf_round(r[i].y); l.y = r[i].y - h.y;
        h.z = tf_round(r[i].z); l.z = r[i].z - h.z;
        h.w = tf_round(r[i].w); l.w = r[i].w - h.w;
        *reinterpret_cast<float4*>(hi + row * LDT + kq * 4) = h;
        *reinterpret_cast<float4*>(lo + row * LDT + kq * 4) = l;
    }
}
// B transpose: W row-major [K, ldb]; rows k0..k0+31, cols nb..nb+127 -> [n][k]
template<int NT>
__device__ __forceinline__ void ldg_tileB(const float* __restrict__ W, int ldb, int nb,
                                          int k0, int tid, float4* r)
{
#pragma unroll
    for (int i = 0; i < 1024 / NT; ++i) {
        const int idx = tid + i * NT;
        const int n  = idx & 127;
        const int kg = (idx >> 7) * 4;
        const float* src = W + (size_t)(k0 + kg) * ldb + nb + n;
        r[i].x = src[0];
        r[i].y = src[(size_t)ldb];
        r[i].z = src[(size_t)2 * ldb];
        r[i].w = src[(size_t)3 * ldb];
    }
}
template<int NT>
__device__ __forceinline__ void sts_tileB_split(float* __restrict__ hi, float* __restrict__ lo,
                                                int tid, const float4* r)
{
#pragma unroll
    for (int i = 0; i < 1024 / NT; ++i) {
        const int idx = tid + i * NT;
        const int n  = idx & 127;
        const int kg = (idx >> 7) * 4;
        float4 h, l;
        h.x = tf_round(r[i].x); l.x = r[i].x - h.x;
        h.y = tf_round(r[i].y); l.y = r[i].y - h.y;
        h.z = tf_round(r[i].z); l.z = r[i].z - h.z;
        h.w = tf_round(r[i].w); l.w = r[i].w - h.w;
        *reinterpret_cast<float4*>(hi + n * LDT + kg) = h;
        *reinterpret_cast<float4*>(lo + n * LDT + kg) = l;
    }
}
template<int NT>
__device__ __forceinline__ void sts_tileB_raw(float* __restrict__ dst, int tid, const float4* r)
{
#pragma unroll
    for (int i = 0; i < 1024 / NT; ++i) {
        const int idx = tid + i * NT;
        const int n  = idx & 127;
        const int kg = (idx >> 7) * 4;
        *reinterpret_cast<float4*>(dst + n * LDT + kg) = r[i];
    }
}

// ---- fragment loads (k-lane permuted pairs; A and B share the permutation) ----
__device__ __forceinline__ void ldA_p(const float* __restrict__ s, int row0, int kc,
                                      int gid, int tig, uint32_t* a)
{
    float2 v0 = *reinterpret_cast<const float2*>(s + (row0 + gid)     * LDT + kc + 2 * tig);
    float2 v1 = *reinterpret_cast<const float2*>(s + (row0 + gid + 8) * LDT + kc + 2 * tig);
    a[0] = __float_as_uint(v0.x); a[2] = __float_as_uint(v0.y);
    a[1] = __float_as_uint(v1.x); a[3] = __float_as_uint(v1.y);
}
__device__ __forceinline__ void ldB_p(const float* __restrict__ s, int n0, int kc,
                                      int gid, int tig, uint32_t* b)
{
    float2 v = *reinterpret_cast<const float2*>(s + (n0 + gid) * LDT + kc + 2 * tig);
    b[0] = __float_as_uint(v.x); b[1] = __float_as_uint(v.y);
}

// ---- 128-row x 32-col warp-tile chunk variants; MT = number of m16 tiles ----
template<int MT>
__device__ __forceinline__ void chunk_rn(const float* __restrict__ cA, const float* __restrict__ cB,
                                         int wm, int wn, int gid, int tig, float (&acc)[MT][4][4])
{
#pragma unroll
    for (int ks = 0; ks < 4; ++ks) {
        const int kc = ks * 8;
        uint32_t af[MT][4], bf[4][2];
#pragma unroll
        for (int mt = 0; mt < MT; ++mt) ldA_p(cA, wm + mt * 16, kc, gid, tig, af[mt]);
#pragma unroll
        for (int nl = 0; nl < 4; ++nl) ldB_p(cB, wn + nl * 8, kc, gid, tig, bf[nl]);
#pragma unroll
        for (int mt = 0; mt < MT; ++mt)
#pragma unroll
            for (int nl = 0; nl < 4; ++nl)
                mma_tf32(acc[mt][nl], af[mt], bf[nl]);
    }
}
template<int MT>
__device__ __forceinline__ void chunk_x3(const float* __restrict__ cAh, const float* __restrict__ cAl,
                                         const float* __restrict__ cBh, const float* __restrict__ cBl,
                                         int wm, int wn, int gid, int tig, float (&acc)[MT][4][4])
{
#pragma unroll
    for (int ks = 0; ks < 4; ++ks) {
        const int kc = ks * 8;
        uint32_t ah[MT][4], al[MT][4], bh[4][2], bl[4][2];
#pragma unroll
        for (int mt = 0; mt < MT; ++mt) {
            ldA_p(cAh, wm + mt * 16, kc, gid, tig, ah[mt]);
            ldA_p(cAl, wm + mt * 16, kc, gid, tig, al[mt]);
        }
#pragma unroll
        for (int nl = 0; nl < 4; ++nl) {
            ldB_p(cBh, wn + nl * 8, kc, gid, tig, bh[nl]);
            ldB_p(cBl, wn + nl * 8, kc, gid, tig, bl[nl]);
        }
#pragma unroll
        for (int mt = 0; mt < MT; ++mt)
#pragma unroll
            for (int nl = 0; nl < 4; ++nl) {
                mma_tf32(acc[mt][nl], al[mt], bh[nl]);
                mma_tf32(acc[mt][nl], ah[mt], bl[nl]);
                mma_tf32(acc[mt][nl], ah[mt], bh[nl]);
            }
    }
}
template<int MT>
__device__ __forceinline__ void chunk_x2(const float* __restrict__ cAh, const float* __restrict__ cAl,
                                         const float* __restrict__ cBh,
                                         int wm, int wn, int gid, int tig, float (&acc)[MT][4][4])
{
#pragma unroll
    for (int ks = 0; ks < 4; ++ks) {
        const int kc = ks * 8;
        uint32_t ah[MT][4], al[MT][4], bh[4][2];
#pragma unroll
        for (int mt = 0; mt < MT; ++mt) {
            ldA_p(cAh, wm + mt * 16, kc, gid, tig, ah[mt]);
            ldA_p(cAl, wm + mt * 16, kc, gid, tig, al[mt]);
        }
#pragma unroll
        for (int nl = 0; nl < 4; ++nl) ldB_p(cBh, wn + nl * 8, kc, gid, tig, bh[nl]);
#pragma unroll
        for (int mt = 0; mt < MT; ++mt)
#pragma unroll
            for (int nl = 0; nl < 4; ++nl) {
                mma_tf32(acc[mt][nl], al[mt], bh[nl]);
                mma_tf32(acc[mt][nl], ah[mt], bh[nl]);
            }
    }
}

// ---------------------------------------------------------------------------
// Fused scores (512 threads, 16 warps 4x4, warp tile 32x32, 1 sync/iter):
// S = (Q·K^T) * (tanhQ·tanhK^T + 1) * 0.03125. grid (32, 32, 4). smem 163840.
// ---------------------------------------------------------------------------
__global__ void __launch_bounds__(512)
scores_tc_kernel(const float* __restrict__ Qm, const float* __restrict__ Km,
                 const float* __restrict__ tQm, const float* __restrict__ tKm,
                 float* __restrict__ S)
{
    extern __shared__ float sm[];
    float* SA1 = sm;
    float* SB1 = sm + 2 * TILE_F;
    float* SA2 = sm + 4 * TILE_F;
    float* SB2 = sm + 6 * TILE_F;
    const uint32_t a1b = (uint32_t)__cvta_generic_to_shared(SA1);
    const uint32_t b1b = (uint32_t)__cvta_generic_to_shared(SB1);
    const uint32_t a2b = (uint32_t)__cvta_generic_to_shared(SA2);
    const uint32_t b2b = (uint32_t)__cvta_generic_to_shared(SB2);

    const int tid  = threadIdx.x;
    const int wid  = tid >> 5;
    const int lane = tid & 31;
    const int gid  = lane >> 2;
    const int tig  = lane & 3;
    const int wm   = (wid & 3) * 32;
    const int wn   = (wid >> 2) * 32;

    const int b  = blockIdx.z;
    const int mb = blockIdx.y * 128;
    const int nb = blockIdx.x * 128;
    const float* A1 = Qm  + (size_t)b * NSEQ * D + (size_t)mb * D;
    const float* B1 = Km  + (size_t)b * NSEQ * D + (size_t)nb * D;
    const float* A2 = tQm + (size_t)b * NSEQ * D + (size_t)mb * D;
    const float* B2 = tKm + (size_t)b * NSEQ * D + (size_t)nb * D;

    float acc1[2][4][4] = {};
    float acc2[2][4][4] = {};

    const int nt = D / KC; // 8
    const uint32_t bufB = (uint32_t)TILE_F * 4;

    tile_cp<512>(A1, D, 0, a1b, tid);
    tile_cp<512>(B1, D, 0, b1b, tid);
    tile_cp<512>(A2, D, 0, a2b, tid);
    tile_cp<512>(B2, D, 0, b2b, tid);
    cp_commit();

    for (int t = 0; t < nt; ++t) {
        const int cur = t & 1;
        cp_wait0();
        __syncthreads();   // cur tiles visible to all; all warps done with nxt buffers
        if (t + 1 < nt) {
            const int k0 = (t + 1) * KC;
            const uint32_t off = (uint32_t)((t + 1) & 1) * bufB;
            tile_cp<512>(A1, D, k0, a1b + off, tid);
            tile_cp<512>(B1, D, k0, b1b + off, tid);
            tile_cp<512>(A2, D, k0, a2b + off, tid);
            tile_cp<512>(B2, D, k0, b2b + off, tid);
            cp_commit();
        }
        chunk_rn<2>(SA1 + cur * TILE_F, SB1 + cur * TILE_F, wm, wn, gid, tig, acc1);
        chunk_rn<2>(SA2 + cur * TILE_F, SB2 + cur * TILE_F, wm, wn, gid, tig, acc2);
    }

    float* Sb = S + (size_t)b * NSEQ * NSEQ;
#pragma unroll
    for (int mt = 0; mt < 2; ++mt) {
        const int row = mb + wm + mt * 16 + gid;
#pragma unroll
        for (int nl = 0; nl < 4; ++nl) {
            const int col = nb + wn + nl * 8 + tig * 2;
            const float* a1 = acc1[mt][nl];
            const float* a2 = acc2[mt][nl];
            float2 v0 = make_float2(a1[0] * (a2[0] + 1.f) * 0.03125f,
                                    a1[1] * (a2[1] + 1.f) * 0.03125f);
            float2 v1 = make_float2(a1[2] * (a2[2] + 1.f) * 0.03125f,
                                    a1[3] * (a2[3] + 1.f) * 0.03125f);
            *reinterpret_cast<float2*>(Sb + (size_t)row * NSEQ + col)       = v0;
            *reinterpret_cast<float2*>(Sb + (size_t)(row + 8) * NSEQ + col) = v1;
        }
    }
}

// ---------------------------------------------------------------------------
// PV (512 threads, x2): Qhat = attn @ Vr. grid (2, 32, 4). smem 122880 B.
// ---------------------------------------------------------------------------
__global__ void __launch_bounds__(512)
pv_tc_kernel(const float* __restrict__ attn, const float* __restrict__ Vr,
             float* __restrict__ Qhat)
{
    extern __shared__ float sm[];
    float* Ah = sm;
    float* Al = sm + 2 * TILE_F;
    float* Bh = sm + 4 * TILE_F;

    const int tid  = threadIdx.x;
    const int wid  = tid >> 5;
    const int lane = tid & 31;
    const int gid  = lane >> 2;
    const int tig  = lane & 3;
    const int wm   = (wid & 3) * 32;
    const int wn   = (wid >> 2) * 32;

    const int b  = blockIdx.z;
    const int mb = blockIdx.y * 128;
    const int nb = blockIdx.x * 128;
    const float* Ab = attn + (size_t)b * NSEQ * NSEQ + (size_t)mb * NSEQ;
    const float* Vb = Vr + (size_t)b * NSEQ * D;

    float acc[2][4][4] = {};
    const int nt = NSEQ / KC; // 128

    float4 rA[2], rB[2];
    ldg_tileA<512>(Ab, NSEQ, 0, tid, rA);
    ldg_tileB<512>(Vb, D, nb, 0, tid, rB);
    sts_tileA_split<512>(Ah, Al, tid, rA);
    sts_tileB_raw<512>(Bh, tid, rB);
    __syncthreads();

    for (int t = 0; t < nt; ++t) {
        const int cur = t & 1;
        const int nxt = cur ^ 1;
        if (t + 1 < nt) {
            ldg_tileA<512>(Ab, NSEQ, (t + 1) * KC, tid, rA);
            ldg_tileB<512>(Vb, D, nb, (t + 1) * KC, tid, rB);
        }
        chunk_x2<2>(Ah + cur * TILE_F, Al + cur * TILE_F, Bh + cur * TILE_F,
                    wm, wn, gid, tig, acc);
        if (t + 1 < nt) {
            sts_tileA_split<512>(Ah + nxt * TILE_F, Al + nxt * TILE_F, tid, rA);
            sts_tileB_raw<512>(Bh + nxt * TILE_F, tid, rB);
        }
        __syncthreads();
    }

    float* Qb = Qhat + (size_t)b * NSEQ * D;
#pragma unroll
    for (int mt = 0; mt < 2; ++mt) {
        const int row = mb + wm + mt * 16 + gid;
#pragma unroll
        for (int nl = 0; nl < 4; ++nl) {
            const int col = nb + wn + nl * 8 + tig * 2;
            const float* a = acc[mt][nl];
            *reinterpret_cast<float2*>(Qb + (size_t)row * D + col)       = make_float2(a[0], a[1]);
            *reinterpret_cast<float2*>(Qb + (size_t)(row + 8) * D + col) = make_float2(a[2], a[3]);
        }
    }
}

// ---------------------------------------------------------------------------
// Projection (256 thr, x3, pre-split smem). grid (2, 128). smem 163840 B.
// ---------------------------------------------------------------------------
__global__ void __launch_bounds__(256)
proj_tc_kernel(const float* __restrict__ X, const float* __restrict__ W,
               const float* __restrict__ bias,
               float* __restrict__ OutF, float* __restrict__ OutR,
               float* __restrict__ TOutR)
{
    extern __shared__ float sm[];
    float* Ah = sm;
    float* Al = sm + 2 * TILE_F;
    float* Bh = sm + 4 * TILE_F;
    float* Bl = sm + 6 * TILE_F;

    const int tid  = threadIdx.x;
    const int wid  = tid >> 5;
    const int lane = tid & 31;
    const int gid  = lane >> 2;
    const int tig  = lane & 3;
    const int wm   = (wid & 1) * 64;
    const int wn   = (wid >> 1) * 32;

    const int mb = blockIdx.y * 128;
    const int nb = blockIdx.x * 128;
    const float* A = X + (size_t)mb * D;

    float acc[4][4][4] = {};
    const int nt = D / KC; // 8

    float4 rA[4], rB[4];
    ldg_tileA<256>(A, D, 0, tid, rA);
    ldg_tileB<256>(W, D, nb, 0, tid, rB);
    sts_tileA_split<256>(Ah, Al, tid, rA);
    sts_tileB_split<256>(Bh, Bl, tid, rB);
    __syncthreads();

    for (int t = 0; t < nt; ++t) {
        const int cur = t & 1;
        const int nxt = cur ^ 1;
        if (t + 1 < nt) {
            ldg_tileA<256>(A, D, (t + 1) * KC, tid, rA);
            ldg_tileB<256>(W, D, nb, (t + 1) * KC, tid, rB);
        }
        chunk_x3<4>(Ah + cur * TILE_F, Al + cur * TILE_F,
                    Bh + cur * TILE_F, Bl + cur * TILE_F, wm, wn, gid, tig, acc);
        if (t + 1 < nt) {
            sts_tileA_split<256>(Ah + nxt * TILE_F, Al + nxt * TILE_F, tid, rA);
            sts_tileB_split<256>(Bh + nxt * TILE_F, Bl + nxt * TILE_F, tid, rB);
        }
        __syncthreads();
    }

#pragma unroll
    for (int mt = 0; mt < 4; ++mt) {
        const int row = mb + wm + mt * 16 + gid;
#pragma unroll
        for (int nl = 0; nl < 4; ++nl) {
            const int col = nb + wn + nl * 8 + tig * 2;
            const float* a = acc[mt][nl];
            const float b0 = bias[col], b1 = bias[col + 1];
            float v00 = a[0] + b0, v01 = a[1] + b1;
            float v10 = a[2] + b0, v11 = a[3] + b1;
            if (OutF) {
                *reinterpret_cast<float2*>(OutF + (size_t)row * D + col)       = make_float2(v00, v01);
                *reinterpret_cast<float2*>(OutF + (size_t)(row + 8) * D + col) = make_float2(v10, v11);
            }
            if (OutR) {
                *reinterpret_cast<float2*>(OutR + (size_t)row * D + col)       = make_float2(tf_round(v00), tf_round(v01));
                *reinterpret_cast<float2*>(OutR + (size_t)(row + 8) * D + col) = make_float2(tf_round(v10), tf_round(v11));
            }
            if (TOutR) {
                *reinterpret_cast<float2*>(TOutR + (size_t)row * D + col)       = make_float2(tf_round(tanhf(v00)), tf_round(tanhf(v01)));
                *reinterpret_cast<float2*>(TOutR + (size_t)(row + 8) * D + col) = make_float2(tf_round(tanhf(v10)), tf_round(tanhf(v11)));
            }
        }
    }
}

// ---------------------------------------------------------------------------
// Dual gate (256 thr, x3). grid (1, 128). smem 163840 B.
// ---------------------------------------------------------------------------
__global__ void __launch_bounds__(256)
dualgate_tc_kernel(const float* __restrict__ X,
                   const float* __restrict__ Wa, const float* __restrict__ ba,
                   const float* __restrict__ Wb, const float* __restrict__ bb,
                   float* __restrict__ OutA, float* __restrict__ OutB)
{
    extern __shared__ float sm[];
    float* Ah  = sm;                    // 2 buffers
    float* Al  = sm + 2 * TILE_F;       // 2 buffers
    float* Bha = sm + 4 * TILE_F;       // single
    float* Bla = sm + 5 * TILE_F;
    float* Bhb = sm + 6 * TILE_F;
    float* Blb = sm + 7 * TILE_F;

    const int tid  = threadIdx.x;
    const int wid  = tid >> 5;
    const int lane = tid & 31;
    const int gid  = lane >> 2;
    const int tig  = lane & 3;
    const int wm   = (wid & 1) * 64;
    const int wn   = (wid >> 1) * 32;

    const int mb = blockIdx.y * 128;
    const float* A = X + (size_t)mb * D;

    float accA[4][4][4] = {};
    float accB[4][4][4] = {};
    const int nt = D / KC; // 8

    {
        float4 r[4];
        ldg_tileA<256>(A, D, 0, tid, r);
        sts_tileA_split<256>(Ah, Al, tid, r);
        ldg_tileB<256>(Wa, OUTC, 0, 0, tid, r);
        sts_tileB_split<256>(Bha, Bla, tid, r);
        ldg_tileB<256>(Wb, OUTC, 0, 0, tid, r);
        sts_tileB_split<256>(Bhb, Blb, tid, r);
    }
    __syncthreads();

    for (int t = 0; t < nt; ++t) {
        const int cur = t & 1;
        const int nxt = cur ^ 1;
        chunk_x3<4>(Ah + cur * TILE_F, Al + cur * TILE_F, Bha, Bla, wm, wn, gid, tig, accA);
        chunk_x3<4>(Ah + cur * TILE_F, Al + cur * TILE_F, Bhb, Blb, wm, wn, gid, tig, accB);
        __syncthreads();
        if (t + 1 < nt) {
            float4 r[4];
            const int k0 = (t + 1) * KC;
            ldg_tileA<256>(A, D, k0, tid, r);
            sts_tileA_split<256>(Ah + nxt * TILE_F, Al + nxt * TILE_F, tid, r);
            ldg_tileB<256>(Wa, OUTC, 0, k0, tid, r);
            sts_tileB_split<256>(Bha, Bla, tid, r);
            ldg_tileB<256>(Wb, OUTC, 0, k0, tid, r);
            sts_tileB_split<256>(Bhb, Blb, tid, r);
        }
        __syncthreads();
    }

#pragma unroll
    for (int mt = 0; mt < 4; ++mt) {
        const int row = mb + wm + mt * 16 + gid;
#pragma unroll
        for (int nl = 0; nl < 4; ++nl) {
            const int col = wn + nl * 8 + tig * 2;
            const float* a = accA[mt][nl];
            const float* c = accB[mt][nl];
            float a0 = ba[col], a1 = ba[col + 1];
            float c0 = bb[col], c1 = bb[col + 1];
            *reinterpret_cast<float2*>(OutA + (size_t)row * OUTC + col) =
                make_float2(relu_f(a[0] + a0), relu_f(a[1] + a1));
            *reinterpret_cast<float2*>(OutA + (size_t)(row + 8) * OUTC + col) =
                make_float2(relu_f(a[2] + a0), relu_f(a[3] + a1));
            *reinterpret_cast<float2*>(OutB + (size_t)row * OUTC + col) =
                make_float2(relu_f(c[0] + c0), relu_f(c[1] + c1));
            *reinterpret_cast<float2*>(OutB + (size_t)(row + 8) * OUTC + col) =
                make_float2(relu_f(c[2] + c0), relu_f(c[3] + c1));
        }
    }
}

// ---------------------------------------------------------------------------
// Final (256 thr, x3): out1 = Qf + relu(GE @ Wc + bc). grid (1, 128). smem 122880 B.
// ---------------------------------------------------------------------------
__global__ void __launch_bounds__(256)
final_tc_kernel(const float* __restrict__ GE, const float* __restrict__ Wc,
                const float* __restrict__ bc, const float* __restrict__ Qf,
                float* __restrict__ Out)
{
    extern __shared__ float sm[];
    float* Ah = sm;                 // 2 buffers
    float* Al = sm + 2 * TILE_F;    // 2 buffers
    float* Bh = sm + 4 * TILE_F;    // single
    float* Bl = sm + 5 * TILE_F;

    const int tid  = threadIdx.x;
    const int wid  = tid >> 5;
    const int lane = tid & 31;
    const int gid  = lane >> 2;
    const int tig  = lane & 3;
    const int wm   = (wid & 1) * 64;
    const int wn   = (wid >> 1) * 32;

    const int mb = blockIdx.y * 128;
    const float* A = GE + (size_t)mb * OUTC;

    float acc[4][4][4] = {};
    const int nt = OUTC / KC; // 4

    {
        float4 r[4];
        ldg_tileA<256>(A, OUTC, 0, tid, r);
        sts_tileA_split<256>(Ah, Al, tid, r);
        ldg_tileB<256>(Wc, OUTC, 0, 0, tid, r);
        sts_tileB_split<256>(Bh, Bl, tid, r);
    }
    __syncthreads();

    for (int t = 0; t < nt; ++t) {
        const int cur = t & 1;
        const int nxt = cur ^ 1;
        chunk_x3<4>(Ah + cur * TILE_F, Al + cur * TILE_F, Bh, Bl, wm, wn, gid, tig, acc);
        __syncthreads();
        if (t + 1 < nt) {
            float4 r[4];
            const int k0 = (t + 1) * KC;
            ldg_tileA<256>(A, OUTC, k0, tid, r);
            sts_tileA_split<256>(Ah + nxt * TILE_F, Al + nxt * TILE_F, tid, r);
            ldg_tileB<256>(Wc, OUTC, 0, k0, tid, r);
            sts_tileB_split<256>(Bh, Bl, tid, r);
        }
        __syncthreads();
    }

#pragma unroll
    for (int mt = 0; mt < 4; ++mt) {
        const int row = mb + wm + mt * 16 + gid;
#pragma unroll
        for (int nl = 0; nl < 4; ++nl) {
            const int col = wn + nl * 8 + tig * 2;
            const float* a = acc[mt][nl];
            const float b0 = bc[col], b1 = bc[col + 1];
            const float* q0 = Qf + (size_t)row * OUTC + col;
            const float* q1 = Qf + (size_t)(row + 8) * OUTC + col;
            *reinterpret_cast<float2*>(Out + (size_t)row * OUTC + col) =
                make_float2(q0[0] + relu_f(a[0] + b0), q0[1] + relu_f(a[1] + b1));
            *reinterpret_cast<float2*>(Out + (size_t)(row + 8) * OUTC + col) =
                make_float2(q1[0] + relu_f(a[2] + b0), q1[1] + relu_f(a[3] + b1));
        }
    }
}

// ---------------------------------------------------------------------------
// Softmax (float4): attn = softmax_row(S). one CTA per row. grid 16384
// ---------------------------------------------------------------------------
__global__ void __launch_bounds__(256)
softmax_kernel(const float* __restrict__ S, float* __restrict__ attn)
{
    __shared__ float4 rowbuf[NSEQ / 4];
    __shared__ float red[8];
    __shared__ float bcast;
    const size_t r = blockIdx.x;
    const float4* ps = reinterpret_cast<const float4*>(S + r * NSEQ);
    float4* po = reinterpret_cast<float4*>(attn + r * NSEQ);
    const int tid = threadIdx.x;

    float m = -1e30f;
    for (int i = tid; i < NSEQ / 4; i += 256) {
        float4 v = ps[i];
        rowbuf[i] = v;
        m = fmaxf(fmaxf(fmaxf(m, v.x), fmaxf(v.y, v.z)), v.w);
    }
#pragma unroll
    for (int off = 16; off; off >>= 1) m = fmaxf(m, __shfl_xor_sync(0xffffffffu, m, off));
    if ((tid & 31) == 0) red[tid >> 5] = m;
    __syncthreads();
    if (tid < 8) {
        float mm = red[tid];
#pragma unroll
        for (int off = 4; off; off >>= 1) mm = fmaxf(mm, __shfl_xor_sync(0xffu, mm, off));
        if (tid == 0) bcast = mm;
    }
    __syncthreads();
    const float M = bcast;

    float s = 0.f;
    for (int i = tid; i < NSEQ / 4; i += 256) {
        float4 v = rowbuf[i];
        v.x = __expf(v.x - M); v.y = __expf(v.y - M);
        v.z = __expf(v.z - M); v.w = __expf(v.w - M);
        rowbuf[i] = v;
        s += v.x + v.y + v.z + v.w;
    }
#pragma unroll
    for (int off = 16; off; off >>= 1) s += __shfl_xor_sync(0xffffffffu, s, off);
    __syncthreads();
    if ((tid & 31) == 0) red[tid >> 5] = s;
    __syncthreads();
    if (tid < 8) {
        float ss = red[tid];
#pragma unroll
        for (int off = 4; off; off >>= 1) ss += __shfl_xor_sync(0xffu, ss, off);
        if (tid == 0) bcast = 1.0f / ss;
    }
    __syncthreads();
    const float inv = bcast;
    for (int i = tid; i < NSEQ / 4; i += 256) {
        float4 v = rowbuf[i];
        v.x *= inv; v.y *= inv; v.z *= inv; v.w *= inv;
        po[i] = v;
    }
}

// ---------------------------------------------------------------------------
// LayerNorm gate: GE = LN(relu(T1+T2)) * LN(relu(T3)). grid 16384, 128 thr
// ---------------------------------------------------------------------------
__global__ void __launch_bounds__(OUTC)
lngate_kernel(const float* __restrict__ T1, const float* __restrict__ T2,
              const float* __restrict__ T3,
              const float* __restrict__ gg, const float* __restrict__ gb,
              const float* __restrict__ eg, const float* __restrict__ eb,
              float* __restrict__ GE)
{
    __shared__ float2 red[4];
    const size_t r = blockIdx.x;
    const int c = threadIdx.x;

    float a = relu_f(T1[r * OUTC + c] + T2[r * OUTC + c]);
    float2 v = make_float2(a, a * a);
#pragma unroll
    for (int off = 16; off; off >>= 1) {
        v.x += __shfl_xor_sync(0xffffffffu, v.x, off);
        v.y += __shfl_xor_sync(0xffffffffu, v.y, off);
    }
    if ((c & 31) == 0) red[c >> 5] = v;
    __syncthreads();
    float sx = red[0].x + red[1].x + red[2].x + red[3].x;
    float sy = red[0].y + red[1].y + red[2].y + red[3].y;
    float mu  = sx * (1.f / OUTC);
    float var = sy * (1.f / OUTC) - mu * mu;
    float g = (a - mu) * rsqrtf(var + 1e-5f) * gg[c] + gb[c];

    float e0 = relu_f(T3[r * OUTC + c]);
    __syncthreads();
    v = make_float2(e0, e0 * e0);
#pragma unroll
    for (int off = 16; off; off >>= 1) {
        v.x += __shfl_xor_sync(0xffffffffu, v.x, off);
        v.y += __shfl_xor_sync(0xffffffffu, v.y, off);
    }
    if ((c & 31) == 0) red[c >> 5] = v;
    __syncthreads();
    sx = red[0].x + red[1].x + red[2].x + red[3].x;
    sy = red[0].y + red[1].y + red[2].y + red[3].y;
    float mu2  = sx * (1.f / OUTC);
    float var2 = sy * (1.f / OUTC) - mu2 * mu2;
    float e = (e0 - mu2) * rsqrtf(var2 + 1e-5f) * eg[c] + eb[c];

    GE[r * OUTC + c] = g * e;
}

// ---------------------------------------------------------------------------
// Launch
// ---------------------------------------------------------------------------
extern "C" void kernel_launch(void* const* d_in, const int* in_sizes, int n_in,
                              void* d_out, int out_size)
{
    const float* x1  = (const float*)d_in[0];
    const float* x2  = (const float*)d_in[1];
    const float* W_q = (const float*)d_in[2];  const float* b_q = (const float*)d_in[3];
    const float* W_k = (const float*)d_in[4];  const float* b_k = (const float*)d_in[5];
    const float* W_v = (const float*)d_in[6];  const float* b_v = (const float*)d_in[7];
    const float* W1  = (const float*)d_in[8];  const float* b1  = (const float*)d_in[9];
    const float* W2  = (const float*)d_in[10]; const float* b2  = (const float*)d_in[11];
    const float* W3  = (const float*)d_in[12]; const float* b3  = (const float*)d_in[13];
    const float* gg  = (const float*)d_in[14]; const float* gb  = (const float*)d_in[15];
    const float* eg  = (const float*)d_in[16]; const float* eb  = (const float*)d_in[17];
    const float* W_c = (const float*)d_in[18]; const float* b_c = (const float*)d_in[19];
    const float* W_f = (const float*)d_in[20]; const float* b_f = (const float*)d_in[21];

    float* out1 = (float*)d_out;
    float* attn = out1 + OUT1_ELEMS;

    void* p;
    cudaGetSymbolAddress(&p, g_Q);    float* Q    = (float*)p;
    cudaGetSymbolAddress(&p, g_Qr);   float* Qr   = (float*)p;
    cudaGetSymbolAddress(&p, g_Kr);   float* Kr   = (float*)p;
    cudaGetSymbolAddress(&p, g_Vr);   float* Vr   = (float*)p;
    cudaGetSymbolAddress(&p, g_tQ);   float* tQ   = (float*)p;
    cudaGetSymbolAddress(&p, g_tK);   float* tK   = (float*)p;
    cudaGetSymbolAddress(&p, g_S);    float* S    = (float*)p;
    cudaGetSymbolAddress(&p, g_Qhat); float* Qhat = (float*)p;
    cudaGetSymbolAddress(&p, g_T1);   float* T1   = (float*)p;
    cudaGetSymbolAddress(&p, g_T2);   float* T2   = (float*)p;
    cudaGetSymbolAddress(&p, g_T3);   float* T3   = (float*)p;
    cudaGetSymbolAddress(&p, g_Qf);   float* Qf   = (float*)p;
    cudaGetSymbolAddress(&p, g_GE);   float* GE   = (float*)p;

    const int smem8 = 8 * TILE_F * (int)sizeof(float);  // 163840
    const int smem6 = 6 * TILE_F * (int)sizeof(float);  // 122880
    cudaFuncSetAttribute(scores_tc_kernel,   cudaFuncAttributeMaxDynamicSharedMemorySize, smem8);
    cudaFuncSetAttribute(proj_tc_kernel,     cudaFuncAttributeMaxDynamicSharedMemorySize, smem8);
    cudaFuncSetAttribute(pv_tc_kernel,       cudaFuncAttributeMaxDynamicSharedMemorySize, smem6);
    cudaFuncSetAttribute(dualgate_tc_kernel, cudaFuncAttributeMaxDynamicSharedMemorySize, smem8);
    cudaFuncSetAttribute(final_tc_kernel,    cudaFuncAttributeMaxDynamicSharedMemorySize, smem6);

    // Projections (x3): Q (full + rounded + tanh), K (rounded + tanh), V (rounded)
    proj_tc_kernel<<<dim3(2, 128), 256, smem8>>>(x2, W_q, b_q, Q,       Qr, tQ);
    proj_tc_kernel<<<dim3(2, 128), 256, smem8>>>(x1, W_k, b_k, nullptr, Kr, tK);
    proj_tc_kernel<<<dim3(2, 128), 256, smem8>>>(x1, W_v, b_v, nullptr, Vr, nullptr);

    // Fused score GEMMs (512 threads) -> combined pre-softmax scores
    scores_tc_kernel<<<dim3(32, 32, 4), 512, smem8>>>(Qr, Kr, tQ, tK, S);

    // Softmax -> attn (output)
    softmax_kernel<<<BATCH * NSEQ, 256>>>(S, attn);

    // Q_hat = attn @ V (512 threads, x2)
    pv_tc_kernel<<<dim3(2, 32, 4), 512, smem6>>>(attn, Vr, Qhat);

    // Gate projections (shared-A dual GEMMs, x3)
    dualgate_tc_kernel<<<dim3(1, 128), 256, smem8>>>(Q,    W1, b1, W_f, b_f, T1, Qf);
    dualgate_tc_kernel<<<dim3(1, 128), 256, smem8>>>(Qhat, W2, b2, W3,  b3,  T2, T3);

    // LayerNorms + gate product
    lngate_kernel<<<BATCH * NSEQ, OUTC>>>(T1, T2, T3, gg, gb, eg, eb, GE);

    // out1 = Qf + relu(GE @ Wc + bc) (x3)
    final_tc_kernel<<<dim3(1, 128), 256, smem6>>>(GE, W_c, b_c, Qf, out1);
}